// round 10
// baseline (speedup 1.0000x reference)
#include <cuda_runtime.h>
#include <cuda_bf16.h>
#include <math.h>
#include <stdint.h>

// ---------------- problem constants ----------------
#define BATCH 4
#define LSEQ  8192
#define EDIM  1024
#define NH    64
#define FD    128
#define MTOT  (BATCH*LSEQ)   // 32768
#define TCH   16             // scan chunk length
#define NC    (LSEQ/TCH)     // 512 chunks per sequence
#define NBH   (BATCH*NH)     // 256 (b,h) pairs

// smem geometry per stage: rows padded to 72 halves = 144 bytes
#define RSTR  144
#define A_H   0
#define A_L   18432
#define B_H   36864
#define B_L   55296
#define STAGE 73728
#define SMEM_BYTES (2*STAGE)

// ---------------- scratch (device globals) ----------------
__device__ __align__(16) float g_q[MTOT*FD];
__device__ __align__(16) float g_a[MTOT*FD];
__device__ __align__(16) float g_k[MTOT*FD];
__device__ __align__(16) float g_v[MTOT*FD];
__device__ __align__(16) float g_to[MTOT*FD];   // tanh(o)

__device__ __align__(16) float g_Ap0[NBH*NC], g_Ap1[NBH*NC];
__device__ __align__(16) float g_L00[NBH*NC], g_L01[NBH*NC], g_L10[NBH*NC], g_L11[NBH*NC];
__device__ __align__(16) float g_I00[NBH*NC], g_I01[NBH*NC], g_I10[NBH*NC], g_I11[NBH*NC];

// transposed + bf16-split weights: [n][e] with e contiguous (col-major B for mma)
__device__ __align__(16) __nv_bfloat16 g_Wth[3][FD*EDIM];
__device__ __align__(16) __nv_bfloat16 g_Wtl[3][FD*EDIM];
__device__ __align__(16) __nv_bfloat16 g_Woth[EDIM*FD];    // [n=1024][k=128]
__device__ __align__(16) __nv_bfloat16 g_Wotl[EDIM*FD];

// ---------------- helpers ----------------
__device__ __forceinline__ uint32_t smem_u32(const void* p) {
    uint32_t a;
    asm("{ .reg .u64 t; cvta.to.shared.u64 t, %1; cvt.u32.u64 %0, t; }" : "=r"(a) : "l"(p));
    return a;
}
__device__ __forceinline__ void sts64(uint32_t addr, uint32_t a, uint32_t b) {
    asm volatile("st.shared.v2.b32 [%0], {%1,%2};" :: "r"(addr), "r"(a), "r"(b) : "memory");
}
__device__ __forceinline__ void cp16(uint32_t saddr, const void* gaddr) {
    asm volatile("cp.async.cg.shared.global [%0], [%1], 16;" :: "r"(saddr), "l"(gaddr) : "memory");
}
__device__ __forceinline__ void cp_commit() {
    asm volatile("cp.async.commit_group;" ::: "memory");
}
__device__ __forceinline__ void cp_wait0() {
    asm volatile("cp.async.wait_group 0;" ::: "memory");
}
__device__ __forceinline__ void ldsm4(uint32_t* r, uint32_t addr) {
    asm volatile("ldmatrix.sync.aligned.m8n8.x4.shared.b16 {%0,%1,%2,%3}, [%4];"
        : "=r"(r[0]), "=r"(r[1]), "=r"(r[2]), "=r"(r[3]) : "r"(addr));
}
__device__ __forceinline__ void mma16816(float* d, const uint32_t* a, uint32_t b0, uint32_t b1) {
    asm volatile(
        "mma.sync.aligned.m16n8k16.row.col.f32.bf16.bf16.f32 "
        "{%0,%1,%2,%3}, {%4,%5,%6,%7}, {%8,%9}, {%0,%1,%2,%3};"
        : "+f"(d[0]), "+f"(d[1]), "+f"(d[2]), "+f"(d[3])
        : "r"(a[0]), "r"(a[1]), "r"(a[2]), "r"(a[3]), "r"(b0), "r"(b1));
}
__device__ __forceinline__ uint32_t pack_bf16(__nv_bfloat16 a, __nv_bfloat16 b) {
    __nv_bfloat162 t; t.x = a; t.y = b;
    return *reinterpret_cast<uint32_t*>(&t);
}
__device__ __forceinline__ void split2(float f0, float f1, uint32_t& hi, uint32_t& lo) {
    __nv_bfloat16 h0 = __float2bfloat16(f0);
    __nv_bfloat16 h1 = __float2bfloat16(f1);
    hi = pack_bf16(h0, h1);
    lo = pack_bf16(__float2bfloat16(f0 - __bfloat162float(h0)),
                   __float2bfloat16(f1 - __bfloat162float(h1)));
}

// fragment-load lane offsets (bytes), shared by both GEMMs
__device__ __forceinline__ uint32_t a_lane_off(int wm, int lid) {
    return (uint32_t)((wm * 32 + (lid & 15)) * RSTR + ((lid >> 4) & 1) * 16);
}
__device__ __forceinline__ uint32_t b_lane_off(int wn, int lid) {
    return (uint32_t)((wn * 64 + ((lid & 16) >> 1) + (lid & 7)) * RSTR + ((lid & 8) << 1));
}

// mainloop step: one k64 chunk's 4 k16 sub-steps on staged smem
__device__ __forceinline__ void gemm_compute64(uint32_t buf, uint32_t aoff, uint32_t boff,
                                               float acc[2][8][4]) {
    #pragma unroll
    for (int kk = 0; kk < 4; kk++) {
        uint32_t kof = kk * 32;
        uint32_t ah0[4], ah1[4], al0[4], al1[4];
        ldsm4(ah0, buf + A_H + aoff + kof);
        ldsm4(ah1, buf + A_H + aoff + 16 * RSTR + kof);
        ldsm4(al0, buf + A_L + aoff + kof);
        ldsm4(al1, buf + A_L + aoff + 16 * RSTR + kof);
        #pragma unroll
        for (int p = 0; p < 4; p++) {
            uint32_t bh[4], bl[4];
            ldsm4(bh, buf + B_H + boff + p * 16 * RSTR + kof);
            ldsm4(bl, buf + B_L + boff + p * 16 * RSTR + kof);
            mma16816(acc[0][2*p],   ah0, bh[0], bh[1]);
            mma16816(acc[0][2*p],   ah0, bl[0], bl[1]);
            mma16816(acc[0][2*p],   al0, bh[0], bh[1]);
            mma16816(acc[1][2*p],   ah1, bh[0], bh[1]);
            mma16816(acc[1][2*p],   ah1, bl[0], bl[1]);
            mma16816(acc[1][2*p],   al1, bh[0], bh[1]);
            mma16816(acc[0][2*p+1], ah0, bh[2], bh[3]);
            mma16816(acc[0][2*p+1], ah0, bl[2], bl[3]);
            mma16816(acc[0][2*p+1], al0, bh[2], bh[3]);
            mma16816(acc[1][2*p+1], ah1, bh[2], bh[3]);
            mma16816(acc[1][2*p+1], ah1, bl[2], bl[3]);
            mma16816(acc[1][2*p+1], al1, bh[2], bh[3]);
        }
    }
}

// ---------------- weight prep: transpose + bf16 split ----------------
__global__ void __launch_bounds__(256) prep_w_kernel(const float* __restrict__ Wq,
                                                     const float* __restrict__ Wf,
                                                     const float* __restrict__ Wi,
                                                     const float* __restrict__ Wo) {
    int idx = blockIdx.x * 256 + threadIdx.x;
    if (idx < 3 * EDIM * FD) {
        int n = idx & 127, e = (idx >> 7) & 1023, w = idx >> 17;
        const float* W = (w == 0) ? Wq : (w == 1) ? Wf : Wi;
        float v = W[e * FD + n];
        __nv_bfloat16 h = __float2bfloat16(v);
        g_Wth[w][n * EDIM + e] = h;
        g_Wtl[w][n * EDIM + e] = __float2bfloat16(v - __bfloat162float(h));
    } else {
        int j = idx - 3 * EDIM * FD;
        int e = j & 1023, f = j >> 10;
        float v = Wo[f * EDIM + e];
        __nv_bfloat16 h = __float2bfloat16(v);
        g_Woth[e * FD + f] = h;
        g_Wotl[e * FD + f] = __float2bfloat16(v - __bfloat162float(h));
    }
}

// ---------------- GEMM1: x @ {Wq,Wf,Wi}, fused activations, pipelined ----------
// grid (3 weights, 256 m-tiles); 256 threads; dyn smem 147456
// A-fill mapping (R8-proven): u = tid + 256*i; row = u>>4 = (tid>>4)+16i; f4 = tid&15
__global__ void __launch_bounds__(256) gemm1_kernel(const float* __restrict__ x) {
    extern __shared__ char dsm[];
    uint32_t sb = smem_u32(dsm);

    int tid = threadIdx.x, wid = tid >> 5, lid = tid & 31;
    int g = lid >> 2, c = lid & 3;
    int wm = wid & 3, wn = wid >> 2;
    int wsel = blockIdx.x;
    int m0 = blockIdx.y * 128;

    const __nv_bfloat16* __restrict__ Wh = g_Wth[wsel];
    const __nv_bfloat16* __restrict__ Wl = g_Wtl[wsel];

    uint32_t aoff = a_lane_off(wm, lid);
    uint32_t boff = b_lane_off(wn, lid);

    // A fill: thread covers rows (tid>>4)+16i, column f4=(tid&15)
    int arow0 = tid >> 4, af4 = tid & 15;
    const float* aptr = x + (size_t)(m0 + arow0) * EDIM + af4 * 4;
    uint32_t asts = arow0 * RSTR + af4 * 8;      // + i*16*RSTR per i

    float acc[2][8][4];
    #pragma unroll
    for (int mt = 0; mt < 2; mt++)
        #pragma unroll
        for (int nt = 0; nt < 8; nt++)
            #pragma unroll
            for (int j = 0; j < 4; j++) acc[mt][nt][j] = 0.f;

    // prologue: A(0) -> regs, B(0) -> stage0 via cp.async
    float4 ra[8];
    #pragma unroll
    for (int i = 0; i < 8; i++)
        ra[i] = *reinterpret_cast<const float4*>(aptr + (size_t)i * 16 * EDIM);
    #pragma unroll
    for (int i = 0; i < 8; i++) {
        int u = tid + 256 * i;
        int split = u >> 10, row = (u >> 3) & 127, seg = u & 7;
        cp16(sb + (split ? B_L : B_H) + row * RSTR + seg * 16,
             (split ? Wl : Wh) + row * EDIM + seg * 8);
    }
    cp_commit();

    for (int ch = 0; ch < EDIM / 64; ch++) {
        uint32_t buf = sb + (ch & 1) * STAGE;
        cp_wait0();
        // STS A(ch) from regs (split fp32 -> bf16 hi/lo); layout matches R8
        #pragma unroll
        for (int i = 0; i < 8; i++) {
            uint32_t h0, l0, h1, l1;
            split2(ra[i].x, ra[i].y, h0, l0);
            split2(ra[i].z, ra[i].w, h1, l1);
            uint32_t off = asts + (uint32_t)i * 16 * RSTR;
            sts64(buf + A_H + off, h0, h1);
            sts64(buf + A_L + off, l0, l1);
        }
        // prefetch A(ch+1) into regs
        if (ch + 1 < EDIM / 64) {
            const float* ap = aptr + (ch + 1) * 64;
            #pragma unroll
            for (int i = 0; i < 8; i++)
                ra[i] = *reinterpret_cast<const float4*>(ap + (size_t)i * 16 * EDIM);
        }
        __syncthreads();
        // issue B(ch+1) into the other stage
        if (ch + 1 < EDIM / 64) {
            uint32_t nbuf = sb + ((ch + 1) & 1) * STAGE;
            int k0n = (ch + 1) * 64;
            #pragma unroll
            for (int i = 0; i < 8; i++) {
                int u = tid + 256 * i;
                int split = u >> 10, row = (u >> 3) & 127, seg = u & 7;
                cp16(nbuf + (split ? B_L : B_H) + row * RSTR + seg * 16,
                     (split ? Wl : Wh) + row * EDIM + k0n + seg * 8);
            }
            cp_commit();
        }
        gemm_compute64(buf, aoff, boff, acc);
    }

    // epilogue: activation + direct stores (D fragment layout)
    const float RS2 = 0.70710678118654752f;
    int row_base = m0 + wm * 32 + g;
    #pragma unroll
    for (int mt = 0; mt < 2; mt++) {
        #pragma unroll
        for (int nt = 0; nt < 8; nt++) {
            int r = row_base + mt * 16;
            int cc = wn * 64 + nt * 8 + 2 * c;
            float* d = acc[mt][nt];
            if (wsel == 0) {
                float q0 = 0.5f * d[0] * (1.0f + erff(d[0] * RS2)) * RS2;
                float q1 = 0.5f * d[1] * (1.0f + erff(d[1] * RS2)) * RS2;
                float q2 = 0.5f * d[2] * (1.0f + erff(d[2] * RS2)) * RS2;
                float q3 = 0.5f * d[3] * (1.0f + erff(d[3] * RS2)) * RS2;
                *(float2*)&g_q[(size_t)r * FD + cc]       = make_float2(q0, q1);
                *(float2*)&g_q[(size_t)(r + 8) * FD + cc] = make_float2(q2, q3);
            } else if (wsel == 1) {
                float s0 = 1.0f / (1.0f + expf(-d[0]));
                float s1 = 1.0f / (1.0f + expf(-d[1]));
                float s2 = 1.0f / (1.0f + expf(-d[2]));
                float s3 = 1.0f / (1.0f + expf(-d[3]));
                *(float2*)&g_a[(size_t)r * FD + cc]       = make_float2(s0 + 1e-6f, s1 + 1e-6f);
                *(float2*)&g_a[(size_t)(r + 8) * FD + cc] = make_float2(s2 + 1e-6f, s3 + 1e-6f);
                *(float2*)&g_k[(size_t)r * FD + cc]       = make_float2(1.0f - s0, 1.0f - s1);
                *(float2*)&g_k[(size_t)(r + 8) * FD + cc] = make_float2(1.0f - s2, 1.0f - s3);
            } else {
                *(float2*)&g_v[(size_t)r * FD + cc]       = make_float2(d[0], d[1]);
                *(float2*)&g_v[(size_t)(r + 8) * FD + cc] = make_float2(d[2], d[3]);
            }
        }
    }
}

// ---------------- GEMM2: tanh_o @ Wo, pipelined ----------------
// grid (8 n-tiles, 256 m-tiles); 256 threads; dyn smem 147456
__global__ void __launch_bounds__(256) gemm2_kernel(float* __restrict__ out) {
    extern __shared__ char dsm[];
    uint32_t sb = smem_u32(dsm);

    int tid = threadIdx.x, wid = tid >> 5, lid = tid & 31;
    int g = lid >> 2, c = lid & 3;
    int wm = wid & 3, wn = wid >> 2;
    int n0 = blockIdx.x * 128;
    int m0 = blockIdx.y * 128;

    uint32_t aoff = a_lane_off(wm, lid);
    uint32_t boff = b_lane_off(wn, lid);

    int arow0 = tid >> 4, af4 = tid & 15;
    const float* aptr = g_to + (size_t)(m0 + arow0) * FD + af4 * 4;
    uint32_t asts = arow0 * RSTR + af4 * 8;

    float acc[2][8][4];
    #pragma unroll
    for (int mt = 0; mt < 2; mt++)
        #pragma unroll
        for (int nt = 0; nt < 8; nt++)
            #pragma unroll
            for (int j = 0; j < 4; j++) acc[mt][nt][j] = 0.f;

    float4 ra[8];
    #pragma unroll
    for (int i = 0; i < 8; i++)
        ra[i] = *reinterpret_cast<const float4*>(aptr + (size_t)i * 16 * FD);
    #pragma unroll
    for (int i = 0; i < 8; i++) {
        int u = tid + 256 * i;
        int split = u >> 10, row = (u >> 3) & 127, seg = u & 7;
        cp16(sb + (split ? B_L : B_H) + row * RSTR + seg * 16,
             (split ? g_Wotl : g_Woth) + (size_t)(n0 + row) * FD + seg * 8);
    }
    cp_commit();

    for (int ch = 0; ch < 2; ch++) {
        uint32_t buf = sb + (ch & 1) * STAGE;
        cp_wait0();
        #pragma unroll
        for (int i = 0; i < 8; i++) {
            uint32_t h0, l0, h1, l1;
            split2(ra[i].x, ra[i].y, h0, l0);
            split2(ra[i].z, ra[i].w, h1, l1);
            uint32_t off = asts + (uint32_t)i * 16 * RSTR;
            sts64(buf + A_H + off, h0, h1);
            sts64(buf + A_L + off, l0, l1);
        }
        if (ch + 1 < 2) {
            const float* ap = aptr + 64;
            #pragma unroll
            for (int i = 0; i < 8; i++)
                ra[i] = *reinterpret_cast<const float4*>(ap + (size_t)i * 16 * FD);
        }
        __syncthreads();
        if (ch + 1 < 2) {
            uint32_t nbuf = sb + STAGE;
            #pragma unroll
            for (int i = 0; i < 8; i++) {
                int u = tid + 256 * i;
                int split = u >> 10, row = (u >> 3) & 127, seg = u & 7;
                cp16(nbuf + (split ? B_L : B_H) + row * RSTR + seg * 16,
                     (split ? g_Wotl : g_Woth) + (size_t)(n0 + row) * FD + 64 + seg * 8);
            }
            cp_commit();
        }
        gemm_compute64(buf, aoff, boff, acc);
    }

    int row_base = m0 + wm * 32 + g;
    #pragma unroll
    for (int mt = 0; mt < 2; mt++) {
        #pragma unroll
        for (int nt = 0; nt < 8; nt++) {
            int r = row_base + mt * 16;
            int cc = n0 + wn * 64 + nt * 8 + 2 * c;
            float* d = acc[mt][nt];
            *(float2*)&out[(size_t)r * EDIM + cc]       = make_float2(d[0], d[1]);
            *(float2*)&out[(size_t)(r + 8) * EDIM + cc] = make_float2(d[2], d[3]);
        }
    }
}

// ---------------- scan pass A: per-chunk local scan ----------------
__global__ void __launch_bounds__(256) scanA_kernel() {
    int t = blockIdx.x;
    int b = threadIdx.x >> 6, h = threadIdx.x & 63;
    size_t base = ((size_t)b * LSEQ + (size_t)t * TCH) * FD + 2 * h;
    float S00 = 0.f, S01 = 0.f, S10 = 0.f, S11 = 0.f, A0 = 1.f, A1 = 1.f;
    #pragma unroll 4
    for (int i = 0; i < TCH; i++) {
        float2 a  = *(const float2*)&g_a[base];
        float2 kk = *(const float2*)&g_k[base];
        float2 vv = *(const float2*)&g_v[base];
        base += FD;
        S00 = a.x * S00 + kk.x * vv.x; S01 = a.x * S01 + kk.x * vv.y;
        S10 = a.y * S10 + kk.y * vv.x; S11 = a.y * S11 + kk.y * vv.y;
        A0 *= a.x; A1 *= a.y;
    }
    int ci = (b * NH + h) * NC + t;
    g_Ap0[ci] = A0;  g_Ap1[ci] = A1;
    g_L00[ci] = S00; g_L01[ci] = S01;
    g_L10[ci] = S10; g_L11[ci] = S11;
}

// ---------------- scan pass B: parallel Kogge-Stone combine over chunks --------
__global__ void __launch_bounds__(NC) scanB_kernel() {
    __shared__ float sA0[NC], sA1[NC];
    __shared__ float s00[NC], s01[NC], s10[NC], s11[NC];
    int bh = blockIdx.x;
    int t = threadIdx.x;
    size_t base = (size_t)bh * NC + t;

    float a0 = g_Ap0[base], a1 = g_Ap1[base];
    float l00 = g_L00[base], l01 = g_L01[base];
    float l10 = g_L10[base], l11 = g_L11[base];
    sA0[t] = a0; sA1[t] = a1;
    s00[t] = l00; s01[t] = l01; s10[t] = l10; s11[t] = l11;
    __syncthreads();

    #pragma unroll
    for (int d = 1; d < NC; d <<= 1) {
        float pa0 = 0.f, pa1 = 0.f, p00 = 0.f, p01 = 0.f, p10 = 0.f, p11 = 0.f;
        if (t >= d) {
            pa0 = sA0[t - d]; pa1 = sA1[t - d];
            p00 = s00[t - d]; p01 = s01[t - d];
            p10 = s10[t - d]; p11 = s11[t - d];
        }
        __syncthreads();
        if (t >= d) {
            l00 = fmaf(a0, p00, l00); l01 = fmaf(a0, p01, l01);
            l10 = fmaf(a1, p10, l10); l11 = fmaf(a1, p11, l11);
            a0 *= pa0; a1 *= pa1;
            sA0[t] = a0; sA1[t] = a1;
            s00[t] = l00; s01[t] = l01; s10[t] = l10; s11[t] = l11;
        }
        __syncthreads();
    }

    float i00 = 0.f, i01 = 0.f, i10 = 0.f, i11 = 0.f;
    if (t > 0) {
        i00 = s00[t - 1]; i01 = s01[t - 1];
        i10 = s10[t - 1]; i11 = s11[t - 1];
    }
    g_I00[base] = i00; g_I01[base] = i01;
    g_I10[base] = i10; g_I11[base] = i11;
}

// ---------------- scan pass C: replay + tanh ----------------
__global__ void __launch_bounds__(256) scanC_kernel() {
    int t = blockIdx.x;
    int b = threadIdx.x >> 6, h = threadIdx.x & 63;
    int ci = (b * NH + h) * NC + t;
    float S00 = g_I00[ci], S01 = g_I01[ci], S10 = g_I10[ci], S11 = g_I11[ci];
    size_t base = ((size_t)b * LSEQ + (size_t)t * TCH) * FD + 2 * h;
    #pragma unroll 4
    for (int i = 0; i < TCH; i++) {
        float2 a  = *(const float2*)&g_a[base];
        float2 kk = *(const float2*)&g_k[base];
        float2 vv = *(const float2*)&g_v[base];
        float2 q  = *(const float2*)&g_q[base];
        S00 = a.x * S00 + kk.x * vv.x; S01 = a.x * S01 + kk.x * vv.y;
        S10 = a.y * S10 + kk.y * vv.x; S11 = a.y * S11 + kk.y * vv.y;
        float ox = q.x * S00 + q.y * S10;
        float oy = q.x * S01 + q.y * S11;
        *(float2*)&g_to[base] = make_float2(tanhf(ox), tanhf(oy));
        base += FD;
    }
}

// ---------------- launch ----------------
extern "C" void kernel_launch(void* const* d_in, const int* in_sizes, int n_in,
                              void* d_out, int out_size) {
    const float* x  = (const float*)d_in[0];
    const float* Wq = (const float*)d_in[1];
    const float* Wf = (const float*)d_in[2];
    const float* Wi = (const float*)d_in[3];
    const float* Wo = (const float*)d_in[4];
    float* out = (float*)d_out;

    static int configured = 0;
    if (!configured) {
        cudaFuncSetAttribute(gemm1_kernel, cudaFuncAttributeMaxDynamicSharedMemorySize, SMEM_BYTES);
        cudaFuncSetAttribute(gemm2_kernel, cudaFuncAttributeMaxDynamicSharedMemorySize, SMEM_BYTES);
        configured = 1;
    }

    prep_w_kernel<<<2048, 256>>>(Wq, Wf, Wi, Wo);
    gemm1_kernel<<<dim3(3, MTOT / 128), 256, SMEM_BYTES>>>(x);
    scanA_kernel<<<NC, 256>>>();
    scanB_kernel<<<NBH, NC>>>();
    scanC_kernel<<<NC, 256>>>();
    gemm2_kernel<<<dim3(8, MTOT / 128), 256, SMEM_BYTES>>>(out);
}

// round 14
// speedup vs baseline: 1.7682x; 1.7682x over previous
#include <cuda_runtime.h>
#include <cuda_bf16.h>
#include <cuda_fp16.h>
#include <math.h>
#include <stdint.h>

// ---------------- problem constants ----------------
#define BATCH 4
#define LSEQ  8192
#define EDIM  1024
#define NH    64
#define FD    128
#define MTOT  (BATCH*LSEQ)   // 32768
#define TCH   16             // scan chunk length
#define NC    (LSEQ/TCH)     // 512 chunks per sequence
#define NBH   (BATCH*NH)     // 256 (b,h) pairs

// smem geometry: rows padded to 72 halves = 144 bytes
#define RSTR  144
#define A_OFF 0
#define B_OFF 18432
#define SMEM_BYTES 36864

// ---------------- scratch (device globals) ----------------
__device__ __align__(16) float g_q[MTOT*FD];
__device__ __align__(16) float g_a[MTOT*FD];
__device__ __align__(16) float g_k[MTOT*FD];
__device__ __align__(16) float g_v[MTOT*FD];
__device__ __align__(16) float g_to[MTOT*FD];   // tanh(o)

__device__ __align__(16) float g_Ap0[NBH*NC], g_Ap1[NBH*NC];
__device__ __align__(16) float g_L00[NBH*NC], g_L01[NBH*NC], g_L10[NBH*NC], g_L11[NBH*NC];
__device__ __align__(16) float g_I00[NBH*NC], g_I01[NBH*NC], g_I10[NBH*NC], g_I11[NBH*NC];

// transposed fp16 weights: [n][e] with e contiguous (col-major B for mma)
__device__ __align__(16) __half g_Wt16[3][FD*EDIM];
__device__ __align__(16) __half g_Wot16[EDIM*FD];    // [n=1024][k=128]

// ---------------- helpers ----------------
__device__ __forceinline__ uint32_t smem_u32(const void* p) {
    uint32_t a;
    asm("{ .reg .u64 t; cvta.to.shared.u64 t, %1; cvt.u32.u64 %0, t; }" : "=r"(a) : "l"(p));
    return a;
}
__device__ __forceinline__ void sts64(uint32_t addr, uint32_t a, uint32_t b) {
    asm volatile("st.shared.v2.b32 [%0], {%1,%2};" :: "r"(addr), "r"(a), "r"(b) : "memory");
}
__device__ __forceinline__ void sts128(uint32_t addr, uint32_t a, uint32_t b, uint32_t c, uint32_t d) {
    asm volatile("st.shared.v4.b32 [%0], {%1,%2,%3,%4};" :: "r"(addr), "r"(a), "r"(b), "r"(c), "r"(d) : "memory");
}
__device__ __forceinline__ void ldsm4(uint32_t* r, uint32_t addr) {
    asm volatile("ldmatrix.sync.aligned.m8n8.x4.shared.b16 {%0,%1,%2,%3}, [%4];"
        : "=r"(r[0]), "=r"(r[1]), "=r"(r[2]), "=r"(r[3]) : "r"(addr));
}
__device__ __forceinline__ void mma16816(float* d, const uint32_t* a, uint32_t b0, uint32_t b1) {
    asm volatile(
        "mma.sync.aligned.m16n8k16.row.col.f32.f16.f16.f32 "
        "{%0,%1,%2,%3}, {%4,%5,%6,%7}, {%8,%9}, {%0,%1,%2,%3};"
        : "+f"(d[0]), "+f"(d[1]), "+f"(d[2]), "+f"(d[3])
        : "r"(a[0]), "r"(a[1]), "r"(a[2]), "r"(a[3]), "r"(b0), "r"(b1));
}
__device__ __forceinline__ uint32_t cvt2h(float f0, float f1) {
    __half2 h = __floats2half2_rn(f0, f1);
    return *reinterpret_cast<uint32_t*>(&h);
}

// fragment-load lane offsets (bytes), shared by both GEMMs
__device__ __forceinline__ uint32_t a_lane_off(int wm, int lid) {
    return (uint32_t)((wm * 32 + (lid & 15)) * RSTR + ((lid >> 4) & 1) * 16);
}
__device__ __forceinline__ uint32_t b_lane_off(int wn, int lid) {
    return (uint32_t)((wn * 64 + ((lid & 16) >> 1) + (lid & 7)) * RSTR + ((lid & 8) << 1));
}

// mainloop step: one k64 chunk's 4 k16 sub-steps on staged smem
__device__ __forceinline__ void gemm_compute64(uint32_t sb, uint32_t aoff, uint32_t boff,
                                               float acc[2][8][4]) {
    #pragma unroll
    for (int kk = 0; kk < 4; kk++) {
        uint32_t kof = kk * 32;
        uint32_t a0[4], a1[4];
        ldsm4(a0, sb + A_OFF + aoff + kof);
        ldsm4(a1, sb + A_OFF + aoff + 16 * RSTR + kof);
        #pragma unroll
        for (int p = 0; p < 4; p++) {
            uint32_t b[4];
            ldsm4(b, sb + B_OFF + boff + p * 16 * RSTR + kof);
            mma16816(acc[0][2*p],   a0, b[0], b[1]);
            mma16816(acc[0][2*p+1], a0, b[2], b[3]);
            mma16816(acc[1][2*p],   a1, b[0], b[1]);
            mma16816(acc[1][2*p+1], a1, b[2], b[3]);
        }
    }
}

// ---------------- weight prep: transpose + fp16 convert ----------------
__global__ void __launch_bounds__(256) prep_w_kernel(const float* __restrict__ Wq,
                                                     const float* __restrict__ Wf,
                                                     const float* __restrict__ Wi,
                                                     const float* __restrict__ Wo) {
    int idx = blockIdx.x * 256 + threadIdx.x;
    if (idx < 3 * EDIM * FD) {
        int n = idx & 127, e = (idx >> 7) & 1023, w = idx >> 17;
        const float* W = (w == 0) ? Wq : (w == 1) ? Wf : Wi;
        g_Wt16[w][n * EDIM + e] = __float2half_rn(W[e * FD + n]);
    } else {
        int j = idx - 3 * EDIM * FD;
        int e = j & 1023, f = j >> 10;
        g_Wot16[e * FD + f] = __float2half_rn(Wo[f * EDIM + e]);
    }
}

// ---------------- GEMM1: x @ {Wq,Wf,Wi}, fused activations ----------------
// grid (3 weights, 256 m-tiles); 256 threads; dyn smem 36864
__global__ void __launch_bounds__(256, 2) gemm1_kernel(const float* __restrict__ x) {
    extern __shared__ char dsm[];
    uint32_t sb = smem_u32(dsm);

    int tid = threadIdx.x, wid = tid >> 5, lid = tid & 31;
    int g = lid >> 2, c = lid & 3;
    int wm = wid & 3, wn = wid >> 2;
    int wsel = blockIdx.x;
    int m0 = blockIdx.y * 128;

    const __half* __restrict__ Wt = g_Wt16[wsel];

    uint32_t aoff = a_lane_off(wm, lid);
    uint32_t boff = b_lane_off(wn, lid);

    float acc[2][8][4];
    #pragma unroll
    for (int mt = 0; mt < 2; mt++)
        #pragma unroll
        for (int nt = 0; nt < 8; nt++)
            #pragma unroll
            for (int j = 0; j < 4; j++) acc[mt][nt][j] = 0.f;

    for (int ch = 0; ch < EDIM / 64; ch++) {
        int k0 = ch * 64;
        // fill A: x [128 rows][64 k] fp32 -> fp16 (2048 float4 groups)
        #pragma unroll
        for (int i = 0; i < 8; i++) {
            int u = tid + 256 * i;
            int row = u >> 4, f4 = u & 15;
            float4 v = *reinterpret_cast<const float4*>(x + (size_t)(m0 + row) * EDIM + k0 + f4 * 4);
            sts64(sb + A_OFF + row * RSTR + f4 * 8, cvt2h(v.x, v.y), cvt2h(v.z, v.w));
        }
        // fill B: Wt [128 n-rows][64 k] fp16 (1024 uint4)
        #pragma unroll
        for (int i = 0; i < 4; i++) {
            int u = tid + 256 * i;
            int row = u >> 3, seg = u & 7;
            uint4 d = *reinterpret_cast<const uint4*>(Wt + row * EDIM + k0 + seg * 8);
            sts128(sb + B_OFF + row * RSTR + seg * 16, d.x, d.y, d.z, d.w);
        }
        __syncthreads();
        gemm_compute64(sb, aoff, boff, acc);
        __syncthreads();
    }

    // epilogue: activation + direct stores (D fragment layout)
    const float RS2 = 0.70710678118654752f;
    int row_base = m0 + wm * 32 + g;
    #pragma unroll
    for (int mt = 0; mt < 2; mt++) {
        #pragma unroll
        for (int nt = 0; nt < 8; nt++) {
            int r = row_base + mt * 16;
            int cc = wn * 64 + nt * 8 + 2 * c;
            float* d = acc[mt][nt];
            if (wsel == 0) {
                float q0 = 0.5f * d[0] * (1.0f + erff(d[0] * RS2)) * RS2;
                float q1 = 0.5f * d[1] * (1.0f + erff(d[1] * RS2)) * RS2;
                float q2 = 0.5f * d[2] * (1.0f + erff(d[2] * RS2)) * RS2;
                float q3 = 0.5f * d[3] * (1.0f + erff(d[3] * RS2)) * RS2;
                *(float2*)&g_q[(size_t)r * FD + cc]       = make_float2(q0, q1);
                *(float2*)&g_q[(size_t)(r + 8) * FD + cc] = make_float2(q2, q3);
            } else if (wsel == 1) {
                float s0 = 1.0f / (1.0f + expf(-d[0]));
                float s1 = 1.0f / (1.0f + expf(-d[1]));
                float s2 = 1.0f / (1.0f + expf(-d[2]));
                float s3 = 1.0f / (1.0f + expf(-d[3]));
                *(float2*)&g_a[(size_t)r * FD + cc]       = make_float2(s0 + 1e-6f, s1 + 1e-6f);
                *(float2*)&g_a[(size_t)(r + 8) * FD + cc] = make_float2(s2 + 1e-6f, s3 + 1e-6f);
                *(float2*)&g_k[(size_t)r * FD + cc]       = make_float2(1.0f - s0, 1.0f - s1);
                *(float2*)&g_k[(size_t)(r + 8) * FD + cc] = make_float2(1.0f - s2, 1.0f - s3);
            } else {
                *(float2*)&g_v[(size_t)r * FD + cc]       = make_float2(d[0], d[1]);
                *(float2*)&g_v[(size_t)(r + 8) * FD + cc] = make_float2(d[2], d[3]);
            }
        }
    }
}

// ---------------- GEMM2: tanh_o @ Wo ----------------
// grid (8 n-tiles, 256 m-tiles); 256 threads; dyn smem 36864
__global__ void __launch_bounds__(256, 2) gemm2_kernel(float* __restrict__ out) {
    extern __shared__ char dsm[];
    uint32_t sb = smem_u32(dsm);

    int tid = threadIdx.x, wid = tid >> 5, lid = tid & 31;
    int g = lid >> 2, c = lid & 3;
    int wm = wid & 3, wn = wid >> 2;
    int n0 = blockIdx.x * 128;
    int m0 = blockIdx.y * 128;

    uint32_t aoff = a_lane_off(wm, lid);
    uint32_t boff = b_lane_off(wn, lid);

    float acc[2][8][4];
    #pragma unroll
    for (int mt = 0; mt < 2; mt++)
        #pragma unroll
        for (int nt = 0; nt < 8; nt++)
            #pragma unroll
            for (int j = 0; j < 4; j++) acc[mt][nt][j] = 0.f;

    for (int ch = 0; ch < 2; ch++) {
        int k0 = ch * 64;
        #pragma unroll
        for (int i = 0; i < 8; i++) {
            int u = tid + 256 * i;
            int row = u >> 4, f4 = u & 15;
            float4 v = *reinterpret_cast<const float4*>(g_to + (size_t)(m0 + row) * FD + k0 + f4 * 4);
            sts64(sb + A_OFF + row * RSTR + f4 * 8, cvt2h(v.x, v.y), cvt2h(v.z, v.w));
        }
        #pragma unroll
        for (int i = 0; i < 4; i++) {
            int u = tid + 256 * i;
            int row = u >> 3, seg = u & 7;
            uint4 d = *reinterpret_cast<const uint4*>(g_Wot16 + (size_t)(n0 + row) * FD + k0 + seg * 8);
            sts128(sb + B_OFF + row * RSTR + seg * 16, d.x, d.y, d.z, d.w);
        }
        __syncthreads();
        gemm_compute64(sb, aoff, boff, acc);
        __syncthreads();
    }

    int row_base = m0 + wm * 32 + g;
    #pragma unroll
    for (int mt = 0; mt < 2; mt++) {
        #pragma unroll
        for (int nt = 0; nt < 8; nt++) {
            int r = row_base + mt * 16;
            int cc = n0 + wn * 64 + nt * 8 + 2 * c;
            float* d = acc[mt][nt];
            *(float2*)&out[(size_t)r * EDIM + cc]       = make_float2(d[0], d[1]);
            *(float2*)&out[(size_t)(r + 8) * EDIM + cc] = make_float2(d[2], d[3]);
        }
    }
}

// ---------------- scan pass A: per-chunk local scan ----------------
__global__ void __launch_bounds__(256) scanA_kernel() {
    int t = blockIdx.x;
    int b = threadIdx.x >> 6, h = threadIdx.x & 63;
    size_t base = ((size_t)b * LSEQ + (size_t)t * TCH) * FD + 2 * h;
    float S00 = 0.f, S01 = 0.f, S10 = 0.f, S11 = 0.f, A0 = 1.f, A1 = 1.f;
    #pragma unroll 4
    for (int i = 0; i < TCH; i++) {
        float2 a  = *(const float2*)&g_a[base];
        float2 kk = *(const float2*)&g_k[base];
        float2 vv = *(const float2*)&g_v[base];
        base += FD;
        S00 = a.x * S00 + kk.x * vv.x; S01 = a.x * S01 + kk.x * vv.y;
        S10 = a.y * S10 + kk.y * vv.x; S11 = a.y * S11 + kk.y * vv.y;
        A0 *= a.x; A1 *= a.y;
    }
    int ci = (b * NH + h) * NC + t;
    g_Ap0[ci] = A0;  g_Ap1[ci] = A1;
    g_L00[ci] = S00; g_L01[ci] = S01;
    g_L10[ci] = S10; g_L11[ci] = S11;
}

// ---------------- scan pass B: parallel Kogge-Stone combine over chunks --------
__global__ void __launch_bounds__(NC) scanB_kernel() {
    __shared__ float sA0[NC], sA1[NC];
    __shared__ float s00[NC], s01[NC], s10[NC], s11[NC];
    int bh = blockIdx.x;
    int t = threadIdx.x;
    size_t base = (size_t)bh * NC + t;

    float a0 = g_Ap0[base], a1 = g_Ap1[base];
    float l00 = g_L00[base], l01 = g_L01[base];
    float l10 = g_L10[base], l11 = g_L11[base];
    sA0[t] = a0; sA1[t] = a1;
    s00[t] = l00; s01[t] = l01; s10[t] = l10; s11[t] = l11;
    __syncthreads();

    #pragma unroll
    for (int d = 1; d < NC; d <<= 1) {
        float pa0 = 0.f, pa1 = 0.f, p00 = 0.f, p01 = 0.f, p10 = 0.f, p11 = 0.f;
        if (t >= d) {
            pa0 = sA0[t - d]; pa1 = sA1[t - d];
            p00 = s00[t - d]; p01 = s01[t - d];
            p10 = s10[t - d]; p11 = s11[t - d];
        }
        __syncthreads();
        if (t >= d) {
            l00 = fmaf(a0, p00, l00); l01 = fmaf(a0, p01, l01);
            l10 = fmaf(a1, p10, l10); l11 = fmaf(a1, p11, l11);
            a0 *= pa0; a1 *= pa1;
            sA0[t] = a0; sA1[t] = a1;
            s00[t] = l00; s01[t] = l01; s10[t] = l10; s11[t] = l11;
        }
        __syncthreads();
    }

    float i00 = 0.f, i01 = 0.f, i10 = 0.f, i11 = 0.f;
    if (t > 0) {
        i00 = s00[t - 1]; i01 = s01[t - 1];
        i10 = s10[t - 1]; i11 = s11[t - 1];
    }
    g_I00[base] = i00; g_I01[base] = i01;
    g_I10[base] = i10; g_I11[base] = i11;
}

// ---------------- scan pass C: replay + tanh ----------------
__global__ void __launch_bounds__(256) scanC_kernel() {
    int t = blockIdx.x;
    int b = threadIdx.x >> 6, h = threadIdx.x & 63;
    int ci = (b * NH + h) * NC + t;
    float S00 = g_I00[ci], S01 = g_I01[ci], S10 = g_I10[ci], S11 = g_I11[ci];
    size_t base = ((size_t)b * LSEQ + (size_t)t * TCH) * FD + 2 * h;
    #pragma unroll 4
    for (int i = 0; i < TCH; i++) {
        float2 a  = *(const float2*)&g_a[base];
        float2 kk = *(const float2*)&g_k[base];
        float2 vv = *(const float2*)&g_v[base];
        float2 q  = *(const float2*)&g_q[base];
        S00 = a.x * S00 + kk.x * vv.x; S01 = a.x * S01 + kk.x * vv.y;
        S10 = a.y * S10 + kk.y * vv.x; S11 = a.y * S11 + kk.y * vv.y;
        float ox = q.x * S00 + q.y * S10;
        float oy = q.x * S01 + q.y * S11;
        *(float2*)&g_to[base] = make_float2(tanhf(ox), tanhf(oy));
        base += FD;
    }
}

// ---------------- launch ----------------
extern "C" void kernel_launch(void* const* d_in, const int* in_sizes, int n_in,
                              void* d_out, int out_size) {
    const float* x  = (const float*)d_in[0];
    const float* Wq = (const float*)d_in[1];
    const float* Wf = (const float*)d_in[2];
    const float* Wi = (const float*)d_in[3];
    const float* Wo = (const float*)d_in[4];
    float* out = (float*)d_out;

    static int configured = 0;
    if (!configured) {
        cudaFuncSetAttribute(gemm1_kernel, cudaFuncAttributeMaxDynamicSharedMemorySize, SMEM_BYTES);
        cudaFuncSetAttribute(gemm2_kernel, cudaFuncAttributeMaxDynamicSharedMemorySize, SMEM_BYTES);
        configured = 1;
    }

    prep_w_kernel<<<2048, 256>>>(Wq, Wf, Wi, Wo);
    gemm1_kernel<<<dim3(3, MTOT / 128), 256, SMEM_BYTES>>>(x);
    scanA_kernel<<<NC, 256>>>();
    scanB_kernel<<<NBH, NC>>>();
    scanC_kernel<<<NC, 256>>>();
    gemm2_kernel<<<dim3(8, MTOT / 128), 256, SMEM_BYTES>>>(out);
}

// round 15
// speedup vs baseline: 2.0678x; 1.1695x over previous
#include <cuda_runtime.h>
#include <cuda_bf16.h>
#include <cuda_fp16.h>
#include <math.h>
#include <stdint.h>

// ---------------- problem constants ----------------
#define BATCH 4
#define LSEQ  8192
#define EDIM  1024
#define NH    64
#define FD    128
#define MTOT  (BATCH*LSEQ)   // 32768
#define TCH   16             // scan chunk length
#define NC    (LSEQ/TCH)     // 512 chunks per sequence
#define NBH   (BATCH*NH)     // 256 (b,h) pairs

// smem geometry per stage: rows padded to 72 halves = 144 bytes
#define RSTR  144
#define A_OFF 0
#define B_OFF 18432
#define STAGE 36864
#define SMEM_BYTES (2*STAGE)

// ---------------- scratch (device globals) ----------------
__device__ __align__(16) float g_q[MTOT*FD];
__device__ __align__(16) float g_a[MTOT*FD];
__device__ __align__(16) float g_k[MTOT*FD];
__device__ __align__(16) float g_v[MTOT*FD];
__device__ __align__(16) __half g_to[MTOT*FD];   // tanh(o), fp16 (GEMM2 input precision anyway)

__device__ __align__(16) float g_Ap0[NBH*NC], g_Ap1[NBH*NC];
__device__ __align__(16) float g_L00[NBH*NC], g_L01[NBH*NC], g_L10[NBH*NC], g_L11[NBH*NC];
__device__ __align__(16) float g_I00[NBH*NC], g_I01[NBH*NC], g_I10[NBH*NC], g_I11[NBH*NC];

// transposed fp16 weights: [n][e] with e contiguous (col-major B for mma)
__device__ __align__(16) __half g_Wt16[3][FD*EDIM];
__device__ __align__(16) __half g_Wot16[EDIM*FD];    // [n=1024][k=128]

// ---------------- helpers ----------------
__device__ __forceinline__ uint32_t smem_u32(const void* p) {
    uint32_t a;
    asm("{ .reg .u64 t; cvta.to.shared.u64 t, %1; cvt.u32.u64 %0, t; }" : "=r"(a) : "l"(p));
    return a;
}
__device__ __forceinline__ void sts64(uint32_t addr, uint32_t a, uint32_t b) {
    asm volatile("st.shared.v2.b32 [%0], {%1,%2};" :: "r"(addr), "r"(a), "r"(b) : "memory");
}
__device__ __forceinline__ void cp16(uint32_t saddr, const void* gaddr) {
    asm volatile("cp.async.cg.shared.global [%0], [%1], 16;" :: "r"(saddr), "l"(gaddr) : "memory");
}
__device__ __forceinline__ void cp_commit() {
    asm volatile("cp.async.commit_group;" ::: "memory");
}
__device__ __forceinline__ void cp_wait0() {
    asm volatile("cp.async.wait_group 0;" ::: "memory");
}
__device__ __forceinline__ void ldsm4(uint32_t* r, uint32_t addr) {
    asm volatile("ldmatrix.sync.aligned.m8n8.x4.shared.b16 {%0,%1,%2,%3}, [%4];"
        : "=r"(r[0]), "=r"(r[1]), "=r"(r[2]), "=r"(r[3]) : "r"(addr));
}
__device__ __forceinline__ void mma16816(float* d, const uint32_t* a, uint32_t b0, uint32_t b1) {
    asm volatile(
        "mma.sync.aligned.m16n8k16.row.col.f32.f16.f16.f32 "
        "{%0,%1,%2,%3}, {%4,%5,%6,%7}, {%8,%9}, {%0,%1,%2,%3};"
        : "+f"(d[0]), "+f"(d[1]), "+f"(d[2]), "+f"(d[3])
        : "r"(a[0]), "r"(a[1]), "r"(a[2]), "r"(a[3]), "r"(b0), "r"(b1));
}
__device__ __forceinline__ uint32_t cvt2h(float f0, float f1) {
    __half2 h = __floats2half2_rn(f0, f1);
    return *reinterpret_cast<uint32_t*>(&h);
}

// fragment-load lane offsets (bytes), shared by both GEMMs
__device__ __forceinline__ uint32_t a_lane_off(int wm, int lid) {
    return (uint32_t)((wm * 32 + (lid & 15)) * RSTR + ((lid >> 4) & 1) * 16);
}
__device__ __forceinline__ uint32_t b_lane_off(int wn, int lid) {
    return (uint32_t)((wn * 64 + ((lid & 16) >> 1) + (lid & 7)) * RSTR + ((lid & 8) << 1));
}

// mainloop step: one k64 chunk's 4 k16 sub-steps on staged smem
__device__ __forceinline__ void gemm_compute64(uint32_t buf, uint32_t aoff, uint32_t boff,
                                               float acc[2][8][4]) {
    #pragma unroll
    for (int kk = 0; kk < 4; kk++) {
        uint32_t kof = kk * 32;
        uint32_t a0[4], a1[4];
        ldsm4(a0, buf + A_OFF + aoff + kof);
        ldsm4(a1, buf + A_OFF + aoff + 16 * RSTR + kof);
        #pragma unroll
        for (int p = 0; p < 4; p++) {
            uint32_t b[4];
            ldsm4(b, buf + B_OFF + boff + p * 16 * RSTR + kof);
            mma16816(acc[0][2*p],   a0, b[0], b[1]);
            mma16816(acc[0][2*p+1], a0, b[2], b[3]);
            mma16816(acc[1][2*p],   a1, b[0], b[1]);
            mma16816(acc[1][2*p+1], a1, b[2], b[3]);
        }
    }
}

// ---------------- weight prep: transpose + fp16 convert ----------------
__global__ void __launch_bounds__(256) prep_w_kernel(const float* __restrict__ Wq,
                                                     const float* __restrict__ Wf,
                                                     const float* __restrict__ Wi,
                                                     const float* __restrict__ Wo) {
    int idx = blockIdx.x * 256 + threadIdx.x;
    if (idx < 3 * EDIM * FD) {
        int n = idx & 127, e = (idx >> 7) & 1023, w = idx >> 17;
        const float* W = (w == 0) ? Wq : (w == 1) ? Wf : Wi;
        g_Wt16[w][n * EDIM + e] = __float2half_rn(W[e * FD + n]);
    } else {
        int j = idx - 3 * EDIM * FD;
        int e = j & 1023, f = j >> 10;
        g_Wot16[e * FD + f] = __float2half_rn(Wo[f * EDIM + e]);
    }
}

// ---------------- GEMM1: x @ {Wq,Wf,Wi}, fused activations, pipelined ----------
// grid (3 weights, 256 m-tiles); 256 threads; dyn smem 73728; 2 CTAs/SM
__global__ void __launch_bounds__(256, 2) gemm1_kernel(const float* __restrict__ x) {
    extern __shared__ char dsm[];
    uint32_t sb = smem_u32(dsm);

    int tid = threadIdx.x, wid = tid >> 5, lid = tid & 31;
    int g = lid >> 2, c = lid & 3;
    int wm = wid & 3, wn = wid >> 2;
    int wsel = blockIdx.x;
    int m0 = blockIdx.y * 128;

    const __half* __restrict__ Wt = g_Wt16[wsel];

    uint32_t aoff = a_lane_off(wm, lid);
    uint32_t boff = b_lane_off(wn, lid);

    // A fill mapping: thread covers rows (tid>>4)+16i, float4-col f4=(tid&15)
    int arow0 = tid >> 4, af4 = tid & 15;
    const float* aptr = x + (size_t)(m0 + arow0) * EDIM + af4 * 4;
    uint32_t asts = arow0 * RSTR + af4 * 8;      // + i*16*RSTR per i

    float acc[2][8][4];
    #pragma unroll
    for (int mt = 0; mt < 2; mt++)
        #pragma unroll
        for (int nt = 0; nt < 8; nt++)
            #pragma unroll
            for (int j = 0; j < 4; j++) acc[mt][nt][j] = 0.f;

    // prologue: A(0) -> fp16 regs, B(0) -> stage0 via cp.async
    uint32_t rh[8][2];
    #pragma unroll
    for (int i = 0; i < 8; i++) {
        float4 v = *reinterpret_cast<const float4*>(aptr + (size_t)i * 16 * EDIM);
        rh[i][0] = cvt2h(v.x, v.y); rh[i][1] = cvt2h(v.z, v.w);
    }
    #pragma unroll
    for (int i = 0; i < 4; i++) {
        int u = tid + 256 * i;
        int row = u >> 3, seg = u & 7;
        cp16(sb + B_OFF + row * RSTR + seg * 16, Wt + row * EDIM + seg * 8);
    }
    cp_commit();

    for (int ch = 0; ch < EDIM / 64; ch++) {
        uint32_t buf = sb + (ch & 1) * STAGE;
        cp_wait0();
        // STS A(ch) from fp16 regs
        #pragma unroll
        for (int i = 0; i < 8; i++)
            sts64(buf + A_OFF + asts + (uint32_t)i * 16 * RSTR, rh[i][0], rh[i][1]);
        // prefetch A(ch+1) -> fp16 regs
        if (ch + 1 < EDIM / 64) {
            const float* ap = aptr + (ch + 1) * 64;
            #pragma unroll
            for (int i = 0; i < 8; i++) {
                float4 v = *reinterpret_cast<const float4*>(ap + (size_t)i * 16 * EDIM);
                rh[i][0] = cvt2h(v.x, v.y); rh[i][1] = cvt2h(v.z, v.w);
            }
        }
        __syncthreads();
        // issue B(ch+1) into the other stage
        if (ch + 1 < EDIM / 64) {
            uint32_t nbuf = sb + ((ch + 1) & 1) * STAGE;
            int k0n = (ch + 1) * 64;
            #pragma unroll
            for (int i = 0; i < 4; i++) {
                int u = tid + 256 * i;
                int row = u >> 3, seg = u & 7;
                cp16(nbuf + B_OFF + row * RSTR + seg * 16, Wt + row * EDIM + k0n + seg * 8);
            }
            cp_commit();
        }
        gemm_compute64(buf, aoff, boff, acc);
    }

    // epilogue: activation + direct stores (D fragment layout)
    const float RS2 = 0.70710678118654752f;
    int row_base = m0 + wm * 32 + g;
    #pragma unroll
    for (int mt = 0; mt < 2; mt++) {
        #pragma unroll
        for (int nt = 0; nt < 8; nt++) {
            int r = row_base + mt * 16;
            int cc = wn * 64 + nt * 8 + 2 * c;
            float* d = acc[mt][nt];
            if (wsel == 0) {
                float q0 = 0.5f * d[0] * (1.0f + erff(d[0] * RS2)) * RS2;
                float q1 = 0.5f * d[1] * (1.0f + erff(d[1] * RS2)) * RS2;
                float q2 = 0.5f * d[2] * (1.0f + erff(d[2] * RS2)) * RS2;
                float q3 = 0.5f * d[3] * (1.0f + erff(d[3] * RS2)) * RS2;
                *(float2*)&g_q[(size_t)r * FD + cc]       = make_float2(q0, q1);
                *(float2*)&g_q[(size_t)(r + 8) * FD + cc] = make_float2(q2, q3);
            } else if (wsel == 1) {
                float s0 = 1.0f / (1.0f + expf(-d[0]));
                float s1 = 1.0f / (1.0f + expf(-d[1]));
                float s2 = 1.0f / (1.0f + expf(-d[2]));
                float s3 = 1.0f / (1.0f + expf(-d[3]));
                *(float2*)&g_a[(size_t)r * FD + cc]       = make_float2(s0 + 1e-6f, s1 + 1e-6f);
                *(float2*)&g_a[(size_t)(r + 8) * FD + cc] = make_float2(s2 + 1e-6f, s3 + 1e-6f);
                *(float2*)&g_k[(size_t)r * FD + cc]       = make_float2(1.0f - s0, 1.0f - s1);
                *(float2*)&g_k[(size_t)(r + 8) * FD + cc] = make_float2(1.0f - s2, 1.0f - s3);
            } else {
                *(float2*)&g_v[(size_t)r * FD + cc]       = make_float2(d[0], d[1]);
                *(float2*)&g_v[(size_t)(r + 8) * FD + cc] = make_float2(d[2], d[3]);
            }
        }
    }
}

// ---------------- GEMM2: tanh_o @ Wo, fully cp.async pipelined ----------------
// grid (8 n-tiles, 256 m-tiles); 256 threads; dyn smem 73728; 2 CTAs/SM
__global__ void __launch_bounds__(256, 2) gemm2_kernel(float* __restrict__ out) {
    extern __shared__ char dsm[];
    uint32_t sb = smem_u32(dsm);

    int tid = threadIdx.x, wid = tid >> 5, lid = tid & 31;
    int g = lid >> 2, c = lid & 3;
    int wm = wid & 3, wn = wid >> 2;
    int n0 = blockIdx.x * 128;
    int m0 = blockIdx.y * 128;

    uint32_t aoff = a_lane_off(wm, lid);
    uint32_t boff = b_lane_off(wn, lid);

    float acc[2][8][4];
    #pragma unroll
    for (int mt = 0; mt < 2; mt++)
        #pragma unroll
        for (int nt = 0; nt < 8; nt++)
            #pragma unroll
            for (int j = 0; j < 4; j++) acc[mt][nt][j] = 0.f;

    // fills: A (g_to fp16) and B both via cp.async; 1024 + 1024 16B units
    auto issue_chunk = [&](uint32_t buf, int k0) {
        #pragma unroll
        for (int i = 0; i < 4; i++) {
            int u = tid + 256 * i;
            int row = u >> 3, seg = u & 7;
            cp16(buf + A_OFF + row * RSTR + seg * 16,
                 g_to + (size_t)(m0 + row) * FD + k0 + seg * 8);
            cp16(buf + B_OFF + row * RSTR + seg * 16,
                 g_Wot16 + (size_t)(n0 + row) * FD + k0 + seg * 8);
        }
        cp_commit();
    };

    issue_chunk(sb, 0);
    issue_chunk(sb + STAGE, 64);   // both stages in flight; wait peels per-group

    // wait for both groups (chunk0 + chunk1): wait_group 1 leaves newest pending
    asm volatile("cp.async.wait_group 1;" ::: "memory");
    __syncthreads();
    gemm_compute64(sb, aoff, boff, acc);
    cp_wait0();
    __syncthreads();
    gemm_compute64(sb + STAGE, aoff, boff, acc);

    int row_base = m0 + wm * 32 + g;
    #pragma unroll
    for (int mt = 0; mt < 2; mt++) {
        #pragma unroll
        for (int nt = 0; nt < 8; nt++) {
            int r = row_base + mt * 16;
            int cc = n0 + wn * 64 + nt * 8 + 2 * c;
            float* d = acc[mt][nt];
            *(float2*)&out[(size_t)r * EDIM + cc]       = make_float2(d[0], d[1]);
            *(float2*)&out[(size_t)(r + 8) * EDIM + cc] = make_float2(d[2], d[3]);
        }
    }
}

// ---------------- scan pass A: per-chunk local scan ----------------
__global__ void __launch_bounds__(256) scanA_kernel() {
    int t = blockIdx.x;
    int b = threadIdx.x >> 6, h = threadIdx.x & 63;
    size_t base = ((size_t)b * LSEQ + (size_t)t * TCH) * FD + 2 * h;
    float S00 = 0.f, S01 = 0.f, S10 = 0.f, S11 = 0.f, A0 = 1.f, A1 = 1.f;
    #pragma unroll 4
    for (int i = 0; i < TCH; i++) {
        float2 a  = *(const float2*)&g_a[base];
        float2 kk = *(const float2*)&g_k[base];
        float2 vv = *(const float2*)&g_v[base];
        base += FD;
        S00 = a.x * S00 + kk.x * vv.x; S01 = a.x * S01 + kk.x * vv.y;
        S10 = a.y * S10 + kk.y * vv.x; S11 = a.y * S11 + kk.y * vv.y;
        A0 *= a.x; A1 *= a.y;
    }
    int ci = (b * NH + h) * NC + t;
    g_Ap0[ci] = A0;  g_Ap1[ci] = A1;
    g_L00[ci] = S00; g_L01[ci] = S01;
    g_L10[ci] = S10; g_L11[ci] = S11;
}

// ---------------- scan pass B: parallel Kogge-Stone combine over chunks --------
__global__ void __launch_bounds__(NC) scanB_kernel() {
    __shared__ float sA0[NC], sA1[NC];
    __shared__ float s00[NC], s01[NC], s10[NC], s11[NC];
    int bh = blockIdx.x;
    int t = threadIdx.x;
    size_t base = (size_t)bh * NC + t;

    float a0 = g_Ap0[base], a1 = g_Ap1[base];
    float l00 = g_L00[base], l01 = g_L01[base];
    float l10 = g_L10[base], l11 = g_L11[base];
    sA0[t] = a0; sA1[t] = a1;
    s00[t] = l00; s01[t] = l01; s10[t] = l10; s11[t] = l11;
    __syncthreads();

    #pragma unroll
    for (int d = 1; d < NC; d <<= 1) {
        float pa0 = 0.f, pa1 = 0.f, p00 = 0.f, p01 = 0.f, p10 = 0.f, p11 = 0.f;
        if (t >= d) {
            pa0 = sA0[t - d]; pa1 = sA1[t - d];
            p00 = s00[t - d]; p01 = s01[t - d];
            p10 = s10[t - d]; p11 = s11[t - d];
        }
        __syncthreads();
        if (t >= d) {
            l00 = fmaf(a0, p00, l00); l01 = fmaf(a0, p01, l01);
            l10 = fmaf(a1, p10, l10); l11 = fmaf(a1, p11, l11);
            a0 *= pa0; a1 *= pa1;
            sA0[t] = a0; sA1[t] = a1;
            s00[t] = l00; s01[t] = l01; s10[t] = l10; s11[t] = l11;
        }
        __syncthreads();
    }

    float i00 = 0.f, i01 = 0.f, i10 = 0.f, i11 = 0.f;
    if (t > 0) {
        i00 = s00[t - 1]; i01 = s01[t - 1];
        i10 = s10[t - 1]; i11 = s11[t - 1];
    }
    g_I00[base] = i00; g_I01[base] = i01;
    g_I10[base] = i10; g_I11[base] = i11;
}

// ---------------- scan pass C: replay + tanh (fp16 output) ----------------
__global__ void __launch_bounds__(256) scanC_kernel() {
    int t = blockIdx.x;
    int b = threadIdx.x >> 6, h = threadIdx.x & 63;
    int ci = (b * NH + h) * NC + t;
    float S00 = g_I00[ci], S01 = g_I01[ci], S10 = g_I10[ci], S11 = g_I11[ci];
    size_t base = ((size_t)b * LSEQ + (size_t)t * TCH) * FD + 2 * h;
    #pragma unroll 4
    for (int i = 0; i < TCH; i++) {
        float2 a  = *(const float2*)&g_a[base];
        float2 kk = *(const float2*)&g_k[base];
        float2 vv = *(const float2*)&g_v[base];
        float2 q  = *(const float2*)&g_q[base];
        S00 = a.x * S00 + kk.x * vv.x; S01 = a.x * S01 + kk.x * vv.y;
        S10 = a.y * S10 + kk.y * vv.x; S11 = a.y * S11 + kk.y * vv.y;
        float ox = q.x * S00 + q.y * S10;
        float oy = q.x * S01 + q.y * S11;
        *reinterpret_cast<__half2*>(&g_to[base]) = __floats2half2_rn(tanhf(ox), tanhf(oy));
        base += FD;
    }
}

// ---------------- launch ----------------
extern "C" void kernel_launch(void* const* d_in, const int* in_sizes, int n_in,
                              void* d_out, int out_size) {
    const float* x  = (const float*)d_in[0];
    const float* Wq = (const float*)d_in[1];
    const float* Wf = (const float*)d_in[2];
    const float* Wi = (const float*)d_in[3];
    const float* Wo = (const float*)d_in[4];
    float* out = (float*)d_out;

    static int configured = 0;
    if (!configured) {
        cudaFuncSetAttribute(gemm1_kernel, cudaFuncAttributeMaxDynamicSharedMemorySize, SMEM_BYTES);
        cudaFuncSetAttribute(gemm2_kernel, cudaFuncAttributeMaxDynamicSharedMemorySize, SMEM_BYTES);
        configured = 1;
    }

    prep_w_kernel<<<2048, 256>>>(Wq, Wf, Wi, Wo);
    gemm1_kernel<<<dim3(3, MTOT / 128), 256, SMEM_BYTES>>>(x);
    scanA_kernel<<<NC, 256>>>();
    scanB_kernel<<<NBH, NC>>>();
    scanC_kernel<<<NC, 256>>>();
    gemm2_kernel<<<dim3(8, MTOT / 128), 256, SMEM_BYTES>>>(out);
}

// round 16
// speedup vs baseline: 2.0937x; 1.0125x over previous
#include <cuda_runtime.h>
#include <cuda_bf16.h>
#include <cuda_fp16.h>
#include <math.h>
#include <stdint.h>

// ---------------- problem constants ----------------
#define BATCH 4
#define LSEQ  8192
#define EDIM  1024
#define NH    64
#define FD    128
#define MTOT  (BATCH*LSEQ)   // 32768
#define TCH   16             // scan chunk length
#define NC    (LSEQ/TCH)     // 512 chunks per sequence
#define NBH   (BATCH*NH)     // 256 (b,h) pairs

// smem geometry per stage: rows padded to 72 halves = 144 bytes
#define RSTR  144
#define A_OFF 0
#define B_OFF 18432
#define STAGE 36864
#define SMEM_BYTES (2*STAGE)

// ---------------- scratch (device globals) ----------------
__device__ __align__(16) __half g_q[MTOT*FD];    // fp16: multiplicative scan input
__device__ __align__(16) float  g_a[MTOT*FD];    // fp32: decay (recurrence-critical)
__device__ __align__(16) __half g_k[MTOT*FD];
__device__ __align__(16) __half g_v[MTOT*FD];
__device__ __align__(16) __half g_to[MTOT*FD];   // tanh(o), fp16

__device__ __align__(16) float g_Ap0[NBH*NC], g_Ap1[NBH*NC];
__device__ __align__(16) float g_L00[NBH*NC], g_L01[NBH*NC], g_L10[NBH*NC], g_L11[NBH*NC];
__device__ __align__(16) float g_I00[NBH*NC], g_I01[NBH*NC], g_I10[NBH*NC], g_I11[NBH*NC];

// transposed fp16 weights: [n][e] with e contiguous (col-major B for mma)
__device__ __align__(16) __half g_Wt16[3][FD*EDIM];
__device__ __align__(16) __half g_Wot16[EDIM*FD];    // [n=1024][k=128]

// ---------------- helpers ----------------
__device__ __forceinline__ uint32_t smem_u32(const void* p) {
    uint32_t a;
    asm("{ .reg .u64 t; cvta.to.shared.u64 t, %1; cvt.u32.u64 %0, t; }" : "=r"(a) : "l"(p));
    return a;
}
__device__ __forceinline__ void sts64(uint32_t addr, uint32_t a, uint32_t b) {
    asm volatile("st.shared.v2.b32 [%0], {%1,%2};" :: "r"(addr), "r"(a), "r"(b) : "memory");
}
__device__ __forceinline__ void cp16(uint32_t saddr, const void* gaddr) {
    asm volatile("cp.async.cg.shared.global [%0], [%1], 16;" :: "r"(saddr), "l"(gaddr) : "memory");
}
__device__ __forceinline__ void cp_commit() {
    asm volatile("cp.async.commit_group;" ::: "memory");
}
__device__ __forceinline__ void cp_wait0() {
    asm volatile("cp.async.wait_group 0;" ::: "memory");
}
__device__ __forceinline__ void ldsm4(uint32_t* r, uint32_t addr) {
    asm volatile("ldmatrix.sync.aligned.m8n8.x4.shared.b16 {%0,%1,%2,%3}, [%4];"
        : "=r"(r[0]), "=r"(r[1]), "=r"(r[2]), "=r"(r[3]) : "r"(addr));
}
__device__ __forceinline__ void mma16816(float* d, const uint32_t* a, uint32_t b0, uint32_t b1) {
    asm volatile(
        "mma.sync.aligned.m16n8k16.row.col.f32.f16.f16.f32 "
        "{%0,%1,%2,%3}, {%4,%5,%6,%7}, {%8,%9}, {%0,%1,%2,%3};"
        : "+f"(d[0]), "+f"(d[1]), "+f"(d[2]), "+f"(d[3])
        : "r"(a[0]), "r"(a[1]), "r"(a[2]), "r"(a[3]), "r"(b0), "r"(b1));
}
__device__ __forceinline__ uint32_t cvt2h(float f0, float f1) {
    __half2 h = __floats2half2_rn(f0, f1);
    return *reinterpret_cast<uint32_t*>(&h);
}

// fragment-load lane offsets (bytes), shared by both GEMMs
__device__ __forceinline__ uint32_t a_lane_off(int wm, int lid) {
    return (uint32_t)((wm * 32 + (lid & 15)) * RSTR + ((lid >> 4) & 1) * 16);
}
__device__ __forceinline__ uint32_t b_lane_off(int wn, int lid) {
    return (uint32_t)((wn * 64 + ((lid & 16) >> 1) + (lid & 7)) * RSTR + ((lid & 8) << 1));
}

// mainloop step: one k64 chunk's 4 k16 sub-steps on staged smem
__device__ __forceinline__ void gemm_compute64(uint32_t buf, uint32_t aoff, uint32_t boff,
                                               float acc[2][8][4]) {
    #pragma unroll
    for (int kk = 0; kk < 4; kk++) {
        uint32_t kof = kk * 32;
        uint32_t a0[4], a1[4];
        ldsm4(a0, buf + A_OFF + aoff + kof);
        ldsm4(a1, buf + A_OFF + aoff + 16 * RSTR + kof);
        #pragma unroll
        for (int p = 0; p < 4; p++) {
            uint32_t b[4];
            ldsm4(b, buf + B_OFF + boff + p * 16 * RSTR + kof);
            mma16816(acc[0][2*p],   a0, b[0], b[1]);
            mma16816(acc[0][2*p+1], a0, b[2], b[3]);
            mma16816(acc[1][2*p],   a1, b[0], b[1]);
            mma16816(acc[1][2*p+1], a1, b[2], b[3]);
        }
    }
}

// ---------------- weight prep: transpose + fp16 convert ----------------
__global__ void __launch_bounds__(256) prep_w_kernel(const float* __restrict__ Wq,
                                                     const float* __restrict__ Wf,
                                                     const float* __restrict__ Wi,
                                                     const float* __restrict__ Wo) {
    int idx = blockIdx.x * 256 + threadIdx.x;
    if (idx < 3 * EDIM * FD) {
        int n = idx & 127, e = (idx >> 7) & 1023, w = idx >> 17;
        const float* W = (w == 0) ? Wq : (w == 1) ? Wf : Wi;
        g_Wt16[w][n * EDIM + e] = __float2half_rn(W[e * FD + n]);
    } else {
        int j = idx - 3 * EDIM * FD;
        int e = j & 1023, f = j >> 10;
        g_Wot16[e * FD + f] = __float2half_rn(Wo[f * EDIM + e]);
    }
}

// ---------------- GEMM1: x @ {Wq,Wf,Wi}, fused activations, pipelined ----------
// grid (3 weights, 256 m-tiles); 256 threads; dyn smem 73728; 2 CTAs/SM
__global__ void __launch_bounds__(256, 2) gemm1_kernel(const float* __restrict__ x) {
    extern __shared__ char dsm[];
    uint32_t sb = smem_u32(dsm);

    int tid = threadIdx.x, wid = tid >> 5, lid = tid & 31;
    int g = lid >> 2, c = lid & 3;
    int wm = wid & 3, wn = wid >> 2;
    int wsel = blockIdx.x;
    int m0 = blockIdx.y * 128;

    const __half* __restrict__ Wt = g_Wt16[wsel];

    uint32_t aoff = a_lane_off(wm, lid);
    uint32_t boff = b_lane_off(wn, lid);

    // A fill mapping: thread covers rows (tid>>4)+16i, float4-col f4=(tid&15)
    int arow0 = tid >> 4, af4 = tid & 15;
    const float* aptr = x + (size_t)(m0 + arow0) * EDIM + af4 * 4;
    uint32_t asts = arow0 * RSTR + af4 * 8;      // + i*16*RSTR per i

    float acc[2][8][4];
    #pragma unroll
    for (int mt = 0; mt < 2; mt++)
        #pragma unroll
        for (int nt = 0; nt < 8; nt++)
            #pragma unroll
            for (int j = 0; j < 4; j++) acc[mt][nt][j] = 0.f;

    // prologue: A(0) -> fp16 regs, B(0) -> stage0 via cp.async
    uint32_t rh[8][2];
    #pragma unroll
    for (int i = 0; i < 8; i++) {
        float4 v = *reinterpret_cast<const float4*>(aptr + (size_t)i * 16 * EDIM);
        rh[i][0] = cvt2h(v.x, v.y); rh[i][1] = cvt2h(v.z, v.w);
    }
    #pragma unroll
    for (int i = 0; i < 4; i++) {
        int u = tid + 256 * i;
        int row = u >> 3, seg = u & 7;
        cp16(sb + B_OFF + row * RSTR + seg * 16, Wt + row * EDIM + seg * 8);
    }
    cp_commit();

    for (int ch = 0; ch < EDIM / 64; ch++) {
        uint32_t buf = sb + (ch & 1) * STAGE;
        cp_wait0();
        // STS A(ch) from fp16 regs
        #pragma unroll
        for (int i = 0; i < 8; i++)
            sts64(buf + A_OFF + asts + (uint32_t)i * 16 * RSTR, rh[i][0], rh[i][1]);
        // prefetch A(ch+1) -> fp16 regs
        if (ch + 1 < EDIM / 64) {
            const float* ap = aptr + (ch + 1) * 64;
            #pragma unroll
            for (int i = 0; i < 8; i++) {
                float4 v = *reinterpret_cast<const float4*>(ap + (size_t)i * 16 * EDIM);
                rh[i][0] = cvt2h(v.x, v.y); rh[i][1] = cvt2h(v.z, v.w);
            }
        }
        __syncthreads();
        // issue B(ch+1) into the other stage
        if (ch + 1 < EDIM / 64) {
            uint32_t nbuf = sb + ((ch + 1) & 1) * STAGE;
            int k0n = (ch + 1) * 64;
            #pragma unroll
            for (int i = 0; i < 4; i++) {
                int u = tid + 256 * i;
                int row = u >> 3, seg = u & 7;
                cp16(nbuf + B_OFF + row * RSTR + seg * 16, Wt + row * EDIM + k0n + seg * 8);
            }
            cp_commit();
        }
        gemm_compute64(buf, aoff, boff, acc);
    }

    // epilogue: activation + direct stores (D fragment layout)
    const float RS2 = 0.70710678118654752f;
    int row_base = m0 + wm * 32 + g;
    #pragma unroll
    for (int mt = 0; mt < 2; mt++) {
        #pragma unroll
        for (int nt = 0; nt < 8; nt++) {
            int r = row_base + mt * 16;
            int cc = wn * 64 + nt * 8 + 2 * c;
            float* d = acc[mt][nt];
            if (wsel == 0) {
                float q0 = 0.5f * d[0] * (1.0f + erff(d[0] * RS2)) * RS2;
                float q1 = 0.5f * d[1] * (1.0f + erff(d[1] * RS2)) * RS2;
                float q2 = 0.5f * d[2] * (1.0f + erff(d[2] * RS2)) * RS2;
                float q3 = 0.5f * d[3] * (1.0f + erff(d[3] * RS2)) * RS2;
                *(__half2*)&g_q[(size_t)r * FD + cc]       = __floats2half2_rn(q0, q1);
                *(__half2*)&g_q[(size_t)(r + 8) * FD + cc] = __floats2half2_rn(q2, q3);
            } else if (wsel == 1) {
                float s0 = 1.0f / (1.0f + expf(-d[0]));
                float s1 = 1.0f / (1.0f + expf(-d[1]));
                float s2 = 1.0f / (1.0f + expf(-d[2]));
                float s3 = 1.0f / (1.0f + expf(-d[3]));
                *(float2*)&g_a[(size_t)r * FD + cc]       = make_float2(s0 + 1e-6f, s1 + 1e-6f);
                *(float2*)&g_a[(size_t)(r + 8) * FD + cc] = make_float2(s2 + 1e-6f, s3 + 1e-6f);
                *(__half2*)&g_k[(size_t)r * FD + cc]       = __floats2half2_rn(1.0f - s0, 1.0f - s1);
                *(__half2*)&g_k[(size_t)(r + 8) * FD + cc] = __floats2half2_rn(1.0f - s2, 1.0f - s3);
            } else {
                *(__half2*)&g_v[(size_t)r * FD + cc]       = __floats2half2_rn(d[0], d[1]);
                *(__half2*)&g_v[(size_t)(r + 8) * FD + cc] = __floats2half2_rn(d[2], d[3]);
            }
        }
    }
}

// ---------------- GEMM2: tanh_o @ Wo, fully cp.async pipelined ----------------
// grid (8 n-tiles, 256 m-tiles); 256 threads; dyn smem 73728; 2 CTAs/SM
__global__ void __launch_bounds__(256, 2) gemm2_kernel(float* __restrict__ out) {
    extern __shared__ char dsm[];
    uint32_t sb = smem_u32(dsm);

    int tid = threadIdx.x, wid = tid >> 5, lid = tid & 31;
    int g = lid >> 2, c = lid & 3;
    int wm = wid & 3, wn = wid >> 2;
    int n0 = blockIdx.x * 128;
    int m0 = blockIdx.y * 128;

    uint32_t aoff = a_lane_off(wm, lid);
    uint32_t boff = b_lane_off(wn, lid);

    float acc[2][8][4];
    #pragma unroll
    for (int mt = 0; mt < 2; mt++)
        #pragma unroll
        for (int nt = 0; nt < 8; nt++)
            #pragma unroll
            for (int j = 0; j < 4; j++) acc[mt][nt][j] = 0.f;

    // fills: A (g_to fp16) and B both via cp.async; 1024 + 1024 16B units
    auto issue_chunk = [&](uint32_t buf, int k0) {
        #pragma unroll
        for (int i = 0; i < 4; i++) {
            int u = tid + 256 * i;
            int row = u >> 3, seg = u & 7;
            cp16(buf + A_OFF + row * RSTR + seg * 16,
                 g_to + (size_t)(m0 + row) * FD + k0 + seg * 8);
            cp16(buf + B_OFF + row * RSTR + seg * 16,
                 g_Wot16 + (size_t)(n0 + row) * FD + k0 + seg * 8);
        }
        cp_commit();
    };

    issue_chunk(sb, 0);
    issue_chunk(sb + STAGE, 64);

    asm volatile("cp.async.wait_group 1;" ::: "memory");
    __syncthreads();
    gemm_compute64(sb, aoff, boff, acc);
    cp_wait0();
    __syncthreads();
    gemm_compute64(sb + STAGE, aoff, boff, acc);

    int row_base = m0 + wm * 32 + g;
    #pragma unroll
    for (int mt = 0; mt < 2; mt++) {
        #pragma unroll
        for (int nt = 0; nt < 8; nt++) {
            int r = row_base + mt * 16;
            int cc = n0 + wn * 64 + nt * 8 + 2 * c;
            float* d = acc[mt][nt];
            *(float2*)&out[(size_t)r * EDIM + cc]       = make_float2(d[0], d[1]);
            *(float2*)&out[(size_t)(r + 8) * EDIM + cc] = make_float2(d[2], d[3]);
        }
    }
}

// ---------------- scan pass A: per-chunk local scan ----------------
__global__ void __launch_bounds__(256) scanA_kernel() {
    int t = blockIdx.x;
    int b = threadIdx.x >> 6, h = threadIdx.x & 63;
    size_t base = ((size_t)b * LSEQ + (size_t)t * TCH) * FD + 2 * h;
    float S00 = 0.f, S01 = 0.f, S10 = 0.f, S11 = 0.f, A0 = 1.f, A1 = 1.f;
    #pragma unroll 4
    for (int i = 0; i < TCH; i++) {
        float2 a  = *(const float2*)&g_a[base];
        float2 kk = __half22float2(*(const __half2*)&g_k[base]);
        float2 vv = __half22float2(*(const __half2*)&g_v[base]);
        base += FD;
        S00 = a.x * S00 + kk.x * vv.x; S01 = a.x * S01 + kk.x * vv.y;
        S10 = a.y * S10 + kk.y * vv.x; S11 = a.y * S11 + kk.y * vv.y;
        A0 *= a.x; A1 *= a.y;
    }
    int ci = (b * NH + h) * NC + t;
    g_Ap0[ci] = A0;  g_Ap1[ci] = A1;
    g_L00[ci] = S00; g_L01[ci] = S01;
    g_L10[ci] = S10; g_L11[ci] = S11;
}

// ---------------- scan pass B: parallel Kogge-Stone combine over chunks --------
__global__ void __launch_bounds__(NC) scanB_kernel() {
    __shared__ float sA0[NC], sA1[NC];
    __shared__ float s00[NC], s01[NC], s10[NC], s11[NC];
    int bh = blockIdx.x;
    int t = threadIdx.x;
    size_t base = (size_t)bh * NC + t;

    float a0 = g_Ap0[base], a1 = g_Ap1[base];
    float l00 = g_L00[base], l01 = g_L01[base];
    float l10 = g_L10[base], l11 = g_L11[base];
    sA0[t] = a0; sA1[t] = a1;
    s00[t] = l00; s01[t] = l01; s10[t] = l10; s11[t] = l11;
    __syncthreads();

    #pragma unroll
    for (int d = 1; d < NC; d <<= 1) {
        float pa0 = 0.f, pa1 = 0.f, p00 = 0.f, p01 = 0.f, p10 = 0.f, p11 = 0.f;
        if (t >= d) {
            pa0 = sA0[t - d]; pa1 = sA1[t - d];
            p00 = s00[t - d]; p01 = s01[t - d];
            p10 = s10[t - d]; p11 = s11[t - d];
        }
        __syncthreads();
        if (t >= d) {
            l00 = fmaf(a0, p00, l00); l01 = fmaf(a0, p01, l01);
            l10 = fmaf(a1, p10, l10); l11 = fmaf(a1, p11, l11);
            a0 *= pa0; a1 *= pa1;
            sA0[t] = a0; sA1[t] = a1;
            s00[t] = l00; s01[t] = l01; s10[t] = l10; s11[t] = l11;
        }
        __syncthreads();
    }

    float i00 = 0.f, i01 = 0.f, i10 = 0.f, i11 = 0.f;
    if (t > 0) {
        i00 = s00[t - 1]; i01 = s01[t - 1];
        i10 = s10[t - 1]; i11 = s11[t - 1];
    }
    g_I00[base] = i00; g_I01[base] = i01;
    g_I10[base] = i10; g_I11[base] = i11;
}

// ---------------- scan pass C: replay + tanh (fp16 output) ----------------
__global__ void __launch_bounds__(256) scanC_kernel() {
    int t = blockIdx.x;
    int b = threadIdx.x >> 6, h = threadIdx.x & 63;
    int ci = (b * NH + h) * NC + t;
    float S00 = g_I00[ci], S01 = g_I01[ci], S10 = g_I10[ci], S11 = g_I11[ci];
    size_t base = ((size_t)b * LSEQ + (size_t)t * TCH) * FD + 2 * h;
    #pragma unroll 4
    for (int i = 0; i < TCH; i++) {
        float2 a  = *(const float2*)&g_a[base];
        float2 kk = __half22float2(*(const __half2*)&g_k[base]);
        float2 vv = __half22float2(*(const __half2*)&g_v[base]);
        float2 q  = __half22float2(*(const __half2*)&g_q[base]);
        S00 = a.x * S00 + kk.x * vv.x; S01 = a.x * S01 + kk.x * vv.y;
        S10 = a.y * S10 + kk.y * vv.x; S11 = a.y * S11 + kk.y * vv.y;
        float ox = q.x * S00 + q.y * S10;
        float oy = q.x * S01 + q.y * S11;
        *reinterpret_cast<__half2*>(&g_to[base]) = __floats2half2_rn(tanhf(ox), tanhf(oy));
        base += FD;
    }
}

// ---------------- launch ----------------
extern "C" void kernel_launch(void* const* d_in, const int* in_sizes, int n_in,
                              void* d_out, int out_size) {
    const float* x  = (const float*)d_in[0];
    const float* Wq = (const float*)d_in[1];
    const float* Wf = (const float*)d_in[2];
    const float* Wi = (const float*)d_in[3];
    const float* Wo = (const float*)d_in[4];
    float* out = (float*)d_out;

    static int configured = 0;
    if (!configured) {
        cudaFuncSetAttribute(gemm1_kernel, cudaFuncAttributeMaxDynamicSharedMemorySize, SMEM_BYTES);
        cudaFuncSetAttribute(gemm2_kernel, cudaFuncAttributeMaxDynamicSharedMemorySize, SMEM_BYTES);
        configured = 1;
    }

    prep_w_kernel<<<2048, 256>>>(Wq, Wf, Wi, Wo);
    gemm1_kernel<<<dim3(3, MTOT / 128), 256, SMEM_BYTES>>>(x);
    scanA_kernel<<<NC, 256>>>();
    scanB_kernel<<<NBH, NC>>>();
    scanC_kernel<<<NC, 256>>>();
    gemm2_kernel<<<dim3(8, MTOT / 128), 256, SMEM_BYTES>>>(out);
}

// round 17
// speedup vs baseline: 2.1176x; 1.0114x over previous
#include <cuda_runtime.h>
#include <cuda_bf16.h>
#include <cuda_fp16.h>
#include <math.h>
#include <stdint.h>

// ---------------- problem constants ----------------
#define BATCH 4
#define LSEQ  8192
#define EDIM  1024
#define NH    64
#define FD    128
#define MTOT  (BATCH*LSEQ)   // 32768
#define TCH   16             // scan chunk length
#define NC    (LSEQ/TCH)     // 512 chunks per sequence
#define NBH   (BATCH*NH)     // 256 (b,h) pairs

// smem geometry per stage: rows padded to 72 halves = 144 bytes
#define RSTR  144
#define A_OFF 0
#define B_OFF 18432
#define STAGE 36864
#define SMEM_BYTES (2*STAGE)

// ---------------- scratch (device globals) ----------------
__device__ __align__(16) __half g_q[MTOT*FD];    // fp16: multiplicative scan input
__device__ __align__(16) float  g_a[MTOT*FD];    // fp32: decay (recurrence-critical)
__device__ __align__(16) __half g_k[MTOT*FD];
__device__ __align__(16) __half g_v[MTOT*FD];
__device__ __align__(16) __half g_to[MTOT*FD];   // tanh(o), fp16

__device__ __align__(16) float g_Ap0[NBH*NC], g_Ap1[NBH*NC];
__device__ __align__(16) float g_L00[NBH*NC], g_L01[NBH*NC], g_L10[NBH*NC], g_L11[NBH*NC];
__device__ __align__(16) float g_I00[NBH*NC], g_I01[NBH*NC], g_I10[NBH*NC], g_I11[NBH*NC];

// transposed fp16 weights: [n][e] with e contiguous (col-major B for mma)
__device__ __align__(16) __half g_Wt16[3][FD*EDIM];
__device__ __align__(16) __half g_Wot16[EDIM*FD];    // [n=1024][k=128]

// monotonic global barrier counter (never reset; deterministic across replays)
__device__ unsigned int g_bar_ctr = 0u;

// ---------------- helpers ----------------
__device__ __forceinline__ uint32_t smem_u32(const void* p) {
    uint32_t a;
    asm("{ .reg .u64 t; cvta.to.shared.u64 t, %1; cvt.u32.u64 %0, t; }" : "=r"(a) : "l"(p));
    return a;
}
__device__ __forceinline__ void sts64(uint32_t addr, uint32_t a, uint32_t b) {
    asm volatile("st.shared.v2.b32 [%0], {%1,%2};" :: "r"(addr), "r"(a), "r"(b) : "memory");
}
__device__ __forceinline__ void cp16(uint32_t saddr, const void* gaddr) {
    asm volatile("cp.async.cg.shared.global [%0], [%1], 16;" :: "r"(saddr), "l"(gaddr) : "memory");
}
__device__ __forceinline__ void cp_commit() {
    asm volatile("cp.async.commit_group;" ::: "memory");
}
__device__ __forceinline__ void cp_wait0() {
    asm volatile("cp.async.wait_group 0;" ::: "memory");
}
__device__ __forceinline__ void ldsm4(uint32_t* r, uint32_t addr) {
    asm volatile("ldmatrix.sync.aligned.m8n8.x4.shared.b16 {%0,%1,%2,%3}, [%4];"
        : "=r"(r[0]), "=r"(r[1]), "=r"(r[2]), "=r"(r[3]) : "r"(addr));
}
__device__ __forceinline__ void mma16816(float* d, const uint32_t* a, uint32_t b0, uint32_t b1) {
    asm volatile(
        "mma.sync.aligned.m16n8k16.row.col.f32.f16.f16.f32 "
        "{%0,%1,%2,%3}, {%4,%5,%6,%7}, {%8,%9}, {%0,%1,%2,%3};"
        : "+f"(d[0]), "+f"(d[1]), "+f"(d[2]), "+f"(d[3])
        : "r"(a[0]), "r"(a[1]), "r"(a[2]), "r"(a[3]), "r"(b0), "r"(b1));
}
__device__ __forceinline__ uint32_t cvt2h(float f0, float f1) {
    __half2 h = __floats2half2_rn(f0, f1);
    return *reinterpret_cast<uint32_t*>(&h);
}
// device-wide barrier; ALL gridDim.x blocks must call. nblocks must divide work.
__device__ __forceinline__ void global_barrier(unsigned int nblocks) {
    __syncthreads();
    if (threadIdx.x == 0) {
        __threadfence();
        unsigned int old = atomicAdd(&g_bar_ctr, 1u);
        unsigned int target = (old / nblocks + 1u) * nblocks;
        unsigned int cur;
        do {
            asm volatile("ld.acquire.gpu.u32 %0, [%1];" : "=r"(cur) : "l"(&g_bar_ctr));
        } while (cur < target);
    }
    __syncthreads();
}

// fragment-load lane offsets (bytes), shared by both GEMMs
__device__ __forceinline__ uint32_t a_lane_off(int wm, int lid) {
    return (uint32_t)((wm * 32 + (lid & 15)) * RSTR + ((lid >> 4) & 1) * 16);
}
__device__ __forceinline__ uint32_t b_lane_off(int wn, int lid) {
    return (uint32_t)((wn * 64 + ((lid & 16) >> 1) + (lid & 7)) * RSTR + ((lid & 8) << 1));
}

// mainloop step: one k64 chunk's 4 k16 sub-steps on staged smem
__device__ __forceinline__ void gemm_compute64(uint32_t buf, uint32_t aoff, uint32_t boff,
                                               float acc[2][8][4]) {
    #pragma unroll
    for (int kk = 0; kk < 4; kk++) {
        uint32_t kof = kk * 32;
        uint32_t a0[4], a1[4];
        ldsm4(a0, buf + A_OFF + aoff + kof);
        ldsm4(a1, buf + A_OFF + aoff + 16 * RSTR + kof);
        #pragma unroll
        for (int p = 0; p < 4; p++) {
            uint32_t b[4];
            ldsm4(b, buf + B_OFF + boff + p * 16 * RSTR + kof);
            mma16816(acc[0][2*p],   a0, b[0], b[1]);
            mma16816(acc[0][2*p+1], a0, b[2], b[3]);
            mma16816(acc[1][2*p],   a1, b[0], b[1]);
            mma16816(acc[1][2*p+1], a1, b[2], b[3]);
        }
    }
}

// ---------------- weight prep: transpose + fp16 convert ----------------
__global__ void __launch_bounds__(256) prep_w_kernel(const float* __restrict__ Wq,
                                                     const float* __restrict__ Wf,
                                                     const float* __restrict__ Wi,
                                                     const float* __restrict__ Wo) {
    int idx = blockIdx.x * 256 + threadIdx.x;
    if (idx < 3 * EDIM * FD) {
        int n = idx & 127, e = (idx >> 7) & 1023, w = idx >> 17;
        const float* W = (w == 0) ? Wq : (w == 1) ? Wf : Wi;
        g_Wt16[w][n * EDIM + e] = __float2half_rn(W[e * FD + n]);
    } else {
        int j = idx - 3 * EDIM * FD;
        int e = j & 1023, f = j >> 10;
        g_Wot16[e * FD + f] = __float2half_rn(Wo[f * EDIM + e]);
    }
}

// ---------------- GEMM1: x @ {Wq,Wf,Wi}, fused activations, pipelined ----------
// grid (3 weights, 256 m-tiles); 256 threads; dyn smem 73728; 2 CTAs/SM
__global__ void __launch_bounds__(256, 2) gemm1_kernel(const float* __restrict__ x) {
    extern __shared__ char dsm[];
    uint32_t sb = smem_u32(dsm);

    int tid = threadIdx.x, wid = tid >> 5, lid = tid & 31;
    int g = lid >> 2, c = lid & 3;
    int wm = wid & 3, wn = wid >> 2;
    int wsel = blockIdx.x;
    int m0 = blockIdx.y * 128;

    const __half* __restrict__ Wt = g_Wt16[wsel];

    uint32_t aoff = a_lane_off(wm, lid);
    uint32_t boff = b_lane_off(wn, lid);

    // A fill mapping: thread covers rows (tid>>4)+16i, float4-col f4=(tid&15)
    int arow0 = tid >> 4, af4 = tid & 15;
    const float* aptr = x + (size_t)(m0 + arow0) * EDIM + af4 * 4;
    uint32_t asts = arow0 * RSTR + af4 * 8;      // + i*16*RSTR per i

    float acc[2][8][4];
    #pragma unroll
    for (int mt = 0; mt < 2; mt++)
        #pragma unroll
        for (int nt = 0; nt < 8; nt++)
            #pragma unroll
            for (int j = 0; j < 4; j++) acc[mt][nt][j] = 0.f;

    // prologue: A(0) -> fp16 regs, B(0) -> stage0 via cp.async
    uint32_t rh[8][2];
    #pragma unroll
    for (int i = 0; i < 8; i++) {
        float4 v = *reinterpret_cast<const float4*>(aptr + (size_t)i * 16 * EDIM);
        rh[i][0] = cvt2h(v.x, v.y); rh[i][1] = cvt2h(v.z, v.w);
    }
    #pragma unroll
    for (int i = 0; i < 4; i++) {
        int u = tid + 256 * i;
        int row = u >> 3, seg = u & 7;
        cp16(sb + B_OFF + row * RSTR + seg * 16, Wt + row * EDIM + seg * 8);
    }
    cp_commit();

    for (int ch = 0; ch < EDIM / 64; ch++) {
        uint32_t buf = sb + (ch & 1) * STAGE;
        cp_wait0();
        // STS A(ch) from fp16 regs
        #pragma unroll
        for (int i = 0; i < 8; i++)
            sts64(buf + A_OFF + asts + (uint32_t)i * 16 * RSTR, rh[i][0], rh[i][1]);
        // prefetch A(ch+1) -> fp16 regs
        if (ch + 1 < EDIM / 64) {
            const float* ap = aptr + (ch + 1) * 64;
            #pragma unroll
            for (int i = 0; i < 8; i++) {
                float4 v = *reinterpret_cast<const float4*>(ap + (size_t)i * 16 * EDIM);
                rh[i][0] = cvt2h(v.x, v.y); rh[i][1] = cvt2h(v.z, v.w);
            }
        }
        __syncthreads();
        // issue B(ch+1) into the other stage
        if (ch + 1 < EDIM / 64) {
            uint32_t nbuf = sb + ((ch + 1) & 1) * STAGE;
            int k0n = (ch + 1) * 64;
            #pragma unroll
            for (int i = 0; i < 4; i++) {
                int u = tid + 256 * i;
                int row = u >> 3, seg = u & 7;
                cp16(nbuf + B_OFF + row * RSTR + seg * 16, Wt + row * EDIM + k0n + seg * 8);
            }
            cp_commit();
        }
        gemm_compute64(buf, aoff, boff, acc);
    }

    // epilogue: activation + direct stores (D fragment layout)
    const float RS2 = 0.70710678118654752f;
    int row_base = m0 + wm * 32 + g;
    #pragma unroll
    for (int mt = 0; mt < 2; mt++) {
        #pragma unroll
        for (int nt = 0; nt < 8; nt++) {
            int r = row_base + mt * 16;
            int cc = wn * 64 + nt * 8 + 2 * c;
            float* d = acc[mt][nt];
            if (wsel == 0) {
                float q0 = 0.5f * d[0] * (1.0f + erff(d[0] * RS2)) * RS2;
                float q1 = 0.5f * d[1] * (1.0f + erff(d[1] * RS2)) * RS2;
                float q2 = 0.5f * d[2] * (1.0f + erff(d[2] * RS2)) * RS2;
                float q3 = 0.5f * d[3] * (1.0f + erff(d[3] * RS2)) * RS2;
                *(__half2*)&g_q[(size_t)r * FD + cc]       = __floats2half2_rn(q0, q1);
                *(__half2*)&g_q[(size_t)(r + 8) * FD + cc] = __floats2half2_rn(q2, q3);
            } else if (wsel == 1) {
                float s0 = 1.0f / (1.0f + expf(-d[0]));
                float s1 = 1.0f / (1.0f + expf(-d[1]));
                float s2 = 1.0f / (1.0f + expf(-d[2]));
                float s3 = 1.0f / (1.0f + expf(-d[3]));
                *(float2*)&g_a[(size_t)r * FD + cc]       = make_float2(s0 + 1e-6f, s1 + 1e-6f);
                *(float2*)&g_a[(size_t)(r + 8) * FD + cc] = make_float2(s2 + 1e-6f, s3 + 1e-6f);
                *(__half2*)&g_k[(size_t)r * FD + cc]       = __floats2half2_rn(1.0f - s0, 1.0f - s1);
                *(__half2*)&g_k[(size_t)(r + 8) * FD + cc] = __floats2half2_rn(1.0f - s2, 1.0f - s3);
            } else {
                *(__half2*)&g_v[(size_t)r * FD + cc]       = __floats2half2_rn(d[0], d[1]);
                *(__half2*)&g_v[(size_t)(r + 8) * FD + cc] = __floats2half2_rn(d[2], d[3]);
            }
        }
    }
}

// ---------------- GEMM2: tanh_o @ Wo, fully cp.async pipelined ----------------
// grid (8 n-tiles, 256 m-tiles); 256 threads; dyn smem 73728; 2 CTAs/SM
__global__ void __launch_bounds__(256, 2) gemm2_kernel(float* __restrict__ out) {
    extern __shared__ char dsm[];
    uint32_t sb = smem_u32(dsm);

    int tid = threadIdx.x, wid = tid >> 5, lid = tid & 31;
    int g = lid >> 2, c = lid & 3;
    int wm = wid & 3, wn = wid >> 2;
    int n0 = blockIdx.x * 128;
    int m0 = blockIdx.y * 128;

    uint32_t aoff = a_lane_off(wm, lid);
    uint32_t boff = b_lane_off(wn, lid);

    float acc[2][8][4];
    #pragma unroll
    for (int mt = 0; mt < 2; mt++)
        #pragma unroll
        for (int nt = 0; nt < 8; nt++)
            #pragma unroll
            for (int j = 0; j < 4; j++) acc[mt][nt][j] = 0.f;

    auto issue_chunk = [&](uint32_t buf, int k0) {
        #pragma unroll
        for (int i = 0; i < 4; i++) {
            int u = tid + 256 * i;
            int row = u >> 3, seg = u & 7;
            cp16(buf + A_OFF + row * RSTR + seg * 16,
                 g_to + (size_t)(m0 + row) * FD + k0 + seg * 8);
            cp16(buf + B_OFF + row * RSTR + seg * 16,
                 g_Wot16 + (size_t)(n0 + row) * FD + k0 + seg * 8);
        }
        cp_commit();
    };

    issue_chunk(sb, 0);
    issue_chunk(sb + STAGE, 64);

    asm volatile("cp.async.wait_group 1;" ::: "memory");
    __syncthreads();
    gemm_compute64(sb, aoff, boff, acc);
    cp_wait0();
    __syncthreads();
    gemm_compute64(sb + STAGE, aoff, boff, acc);

    int row_base = m0 + wm * 32 + g;
    #pragma unroll
    for (int mt = 0; mt < 2; mt++) {
        #pragma unroll
        for (int nt = 0; nt < 8; nt++) {
            int r = row_base + mt * 16;
            int cc = n0 + wn * 64 + nt * 8 + 2 * c;
            float* d = acc[mt][nt];
            *(float2*)&out[(size_t)r * EDIM + cc]       = make_float2(d[0], d[1]);
            *(float2*)&out[(size_t)(r + 8) * EDIM + cc] = make_float2(d[2], d[3]);
        }
    }
}

// ---------------- fused scan: A (local) + B (Kogge-Stone) + C (replay) --------
// grid = NBH(256) blocks x 512 threads; all blocks co-resident -> spin barrier OK
__global__ void __launch_bounds__(512) scan_fused_kernel() {
    __shared__ float sA0[NC], sA1[NC];
    __shared__ float s00[NC], s01[NC], s10[NC], s11[NC];

    int tid = threadIdx.x;
    int bid = blockIdx.x;

    // ---- phase A: local chunk scans (2 chunks per block) ----
    {
        int t = bid * 2 + (tid >> 8);         // chunk index 0..511
        int bh = tid & 255;
        int b = bh >> 6, h = bh & 63;
        size_t base = ((size_t)b * LSEQ + (size_t)t * TCH) * FD + 2 * h;
        float S00 = 0.f, S01 = 0.f, S10 = 0.f, S11 = 0.f, A0 = 1.f, A1 = 1.f;
        #pragma unroll 4
        for (int i = 0; i < TCH; i++) {
            float2 a  = *(const float2*)&g_a[base];
            float2 kk = __half22float2(*(const __half2*)&g_k[base]);
            float2 vv = __half22float2(*(const __half2*)&g_v[base]);
            base += FD;
            S00 = a.x * S00 + kk.x * vv.x; S01 = a.x * S01 + kk.x * vv.y;
            S10 = a.y * S10 + kk.y * vv.x; S11 = a.y * S11 + kk.y * vv.y;
            A0 *= a.x; A1 *= a.y;
        }
        int ci = (b * NH + h) * NC + t;
        g_Ap0[ci] = A0;  g_Ap1[ci] = A1;
        g_L00[ci] = S00; g_L01[ci] = S01;
        g_L10[ci] = S10; g_L11[ci] = S11;
    }

    global_barrier(NBH);

    // ---- phase B: Kogge-Stone combine over chunks for bh = bid ----
    {
        int t = tid;                          // 0..NC-1
        size_t base = (size_t)bid * NC + t;
        float a0 = g_Ap0[base], a1 = g_Ap1[base];
        float l00 = g_L00[base], l01 = g_L01[base];
        float l10 = g_L10[base], l11 = g_L11[base];
        sA0[t] = a0; sA1[t] = a1;
        s00[t] = l00; s01[t] = l01; s10[t] = l10; s11[t] = l11;
        __syncthreads();

        #pragma unroll
        for (int d = 1; d < NC; d <<= 1) {
            float pa0 = 0.f, pa1 = 0.f, p00 = 0.f, p01 = 0.f, p10 = 0.f, p11 = 0.f;
            if (t >= d) {
                pa0 = sA0[t - d]; pa1 = sA1[t - d];
                p00 = s00[t - d]; p01 = s01[t - d];
                p10 = s10[t - d]; p11 = s11[t - d];
            }
            __syncthreads();
            if (t >= d) {
                l00 = fmaf(a0, p00, l00); l01 = fmaf(a0, p01, l01);
                l10 = fmaf(a1, p10, l10); l11 = fmaf(a1, p11, l11);
                a0 *= pa0; a1 *= pa1;
                sA0[t] = a0; sA1[t] = a1;
                s00[t] = l00; s01[t] = l01; s10[t] = l10; s11[t] = l11;
            }
            __syncthreads();
        }

        float i00 = 0.f, i01 = 0.f, i10 = 0.f, i11 = 0.f;
        if (t > 0) {
            i00 = s00[t - 1]; i01 = s01[t - 1];
            i10 = s10[t - 1]; i11 = s11[t - 1];
        }
        g_I00[base] = i00; g_I01[base] = i01;
        g_I10[base] = i10; g_I11[base] = i11;
    }

    global_barrier(NBH);

    // ---- phase C: replay with outputs (2 chunks per block) ----
    {
        int t = bid * 2 + (tid >> 8);
        int bh = tid & 255;
        int b = bh >> 6, h = bh & 63;
        int ci = (b * NH + h) * NC + t;
        float S00 = g_I00[ci], S01 = g_I01[ci], S10 = g_I10[ci], S11 = g_I11[ci];
        size_t base = ((size_t)b * LSEQ + (size_t)t * TCH) * FD + 2 * h;
        #pragma unroll 4
        for (int i = 0; i < TCH; i++) {
            float2 a  = *(const float2*)&g_a[base];
            float2 kk = __half22float2(*(const __half2*)&g_k[base]);
            float2 vv = __half22float2(*(const __half2*)&g_v[base]);
            float2 q  = __half22float2(*(const __half2*)&g_q[base]);
            S00 = a.x * S00 + kk.x * vv.x; S01 = a.x * S01 + kk.x * vv.y;
            S10 = a.y * S10 + kk.y * vv.x; S11 = a.y * S11 + kk.y * vv.y;
            float ox = q.x * S00 + q.y * S10;
            float oy = q.x * S01 + q.y * S11;
            *reinterpret_cast<__half2*>(&g_to[base]) = __floats2half2_rn(tanhf(ox), tanhf(oy));
            base += FD;
        }
    }
}

// ---------------- launch ----------------
extern "C" void kernel_launch(void* const* d_in, const int* in_sizes, int n_in,
                              void* d_out, int out_size) {
    const float* x  = (const float*)d_in[0];
    const float* Wq = (const float*)d_in[1];
    const float* Wf = (const float*)d_in[2];
    const float* Wi = (const float*)d_in[3];
    const float* Wo = (const float*)d_in[4];
    float* out = (float*)d_out;

    static int configured = 0;
    if (!configured) {
        cudaFuncSetAttribute(gemm1_kernel, cudaFuncAttributeMaxDynamicSharedMemorySize, SMEM_BYTES);
        cudaFuncSetAttribute(gemm2_kernel, cudaFuncAttributeMaxDynamicSharedMemorySize, SMEM_BYTES);
        configured = 1;
    }

    prep_w_kernel<<<2048, 256>>>(Wq, Wf, Wi, Wo);
    gemm1_kernel<<<dim3(3, MTOT / 128), 256, SMEM_BYTES>>>(x);
    scan_fused_kernel<<<NBH, 512>>>();
    gemm2_kernel<<<dim3(8, MTOT / 128), 256, SMEM_BYTES>>>(out);
}